// round 4
// baseline (speedup 1.0000x reference)
#include <cuda_runtime.h>
#include <cuda_bf16.h>
#include <math.h>
#include <cstdint>

// ---------------------------------------------------------------------------
// AttentionHead B=4, S=2048, D=1024 — mma.sync bf16 split-precision (bf16x3).
// All GEMMs NT: C[m,n] = scale * sum_k (Ah+Al)[m,k]*(Bh+Bl)[n,k], lo*lo dropped.
// ---------------------------------------------------------------------------

#define B_ 4
#define S_ 2048
#define D_ 1024
#define MS_ (B_ * S_)   // 8192

// ---- scratch (device globals) ----
__device__ __align__(16) __nv_bfloat16 g_qh [(size_t)MS_ * D_];
__device__ __align__(16) __nv_bfloat16 g_ql [(size_t)MS_ * D_];
__device__ __align__(16) __nv_bfloat16 g_kh [(size_t)MS_ * D_];
__device__ __align__(16) __nv_bfloat16 g_kl [(size_t)MS_ * D_];
__device__ __align__(16) __nv_bfloat16 g_vh [(size_t)MS_ * D_];
__device__ __align__(16) __nv_bfloat16 g_vl [(size_t)MS_ * D_];
__device__ __align__(16) __nv_bfloat16 g_wqh[(size_t)D_ * D_];
__device__ __align__(16) __nv_bfloat16 g_wql[(size_t)D_ * D_];
__device__ __align__(16) __nv_bfloat16 g_wkh[(size_t)D_ * D_];
__device__ __align__(16) __nv_bfloat16 g_wkl[(size_t)D_ * D_];
__device__ __align__(16) __nv_bfloat16 g_wvh[(size_t)D_ * D_];
__device__ __align__(16) __nv_bfloat16 g_wvl[(size_t)D_ * D_];
__device__ __align__(16) __nv_bfloat16 g_qph[(size_t)MS_ * D_];
__device__ __align__(16) __nv_bfloat16 g_qpl[(size_t)MS_ * D_];
__device__ __align__(16) __nv_bfloat16 g_kph[(size_t)MS_ * D_];
__device__ __align__(16) __nv_bfloat16 g_kpl[(size_t)MS_ * D_];
__device__ __align__(16) __nv_bfloat16 g_vth[(size_t)D_ * MS_];   // vp^T [D, MS]
__device__ __align__(16) __nv_bfloat16 g_vtl[(size_t)D_ * MS_];
__device__ __align__(16) float         g_s  [(size_t)B_ * S_ * S_];
__device__ __align__(16) __nv_bfloat16 g_ph [(size_t)B_ * S_ * S_];
__device__ __align__(16) __nv_bfloat16 g_pl [(size_t)B_ * S_ * S_];

// ---- helpers ----
__device__ __forceinline__ uint32_t smem_u32(const void* p) {
    uint32_t a;
    asm("{ .reg .u64 t; cvta.to.shared.u64 t, %1; cvt.u32.u64 %0, t; }" : "=r"(a) : "l"(p));
    return a;
}
__device__ __forceinline__ void cp16s(uint32_t dst, const void* src) {
    asm volatile("cp.async.cg.shared.global [%0], [%1], 16;\n" :: "r"(dst), "l"(src));
}
__device__ __forceinline__ void cp_commit() { asm volatile("cp.async.commit_group;\n"); }
template <int N> __device__ __forceinline__ void cp_wait() {
    asm volatile("cp.async.wait_group %0;\n" :: "n"(N));
}
__device__ __forceinline__ void ldsm4(uint32_t (&r)[4], uint32_t addr) {
    asm volatile("ldmatrix.sync.aligned.m8n8.x4.shared.b16 {%0,%1,%2,%3}, [%4];"
                 : "=r"(r[0]), "=r"(r[1]), "=r"(r[2]), "=r"(r[3]) : "r"(addr));
}
__device__ __forceinline__ void mma_bf16(float (&d)[4], const uint32_t (&a)[4],
                                         uint32_t b0, uint32_t b1) {
    asm volatile(
        "mma.sync.aligned.m16n8k16.row.col.f32.bf16.bf16.f32 "
        "{%0,%1,%2,%3}, {%4,%5,%6,%7}, {%8,%9}, {%0,%1,%2,%3};\n"
        : "+f"(d[0]), "+f"(d[1]), "+f"(d[2]), "+f"(d[3])
        : "r"(a[0]), "r"(a[1]), "r"(a[2]), "r"(a[3]), "r"(b0), "r"(b1));
}
__device__ __forceinline__ void split2(float x, __nv_bfloat16& h, __nv_bfloat16& l) {
    h = __float2bfloat16_rn(x);
    l = __float2bfloat16_rn(x - __bfloat162float(h));
}

// ---------------------------------------------------------------------------
// GEMM: BM=BN=128, BK=64 bf16 (128B rows, SW128 swizzle), 3-stage cp.async.
// 8 warps, warp tile 32x64. EPI 0 = fp32*scale, EPI 1 = bf16 hi/lo split.
// ---------------------------------------------------------------------------
constexpr int BKT = 64;
constexpr int SUB = 128 * 128;            // bytes per subtile (128 rows x 128B)
constexpr int STAGE = 4 * SUB;            // Ah, Al, Bh, Bl = 64 KB
constexpr int STAGES = 3;
constexpr int GEMM_SMEM = STAGES * STAGE; // 196608 B

__device__ __forceinline__ void fill_sub(uint32_t dst_base, const __nv_bfloat16* src,
                                         size_t ld, int rowbase, int k0, int tid) {
#pragma unroll
    for (int p = 0; p < 4; p++) {
        int idx = tid + p * 256;          // 0..1023
        int r = idx >> 3, c = idx & 7;    // row 0..127, 16B chunk 0..7
        uint32_t off = (uint32_t)(r * 128 + (((uint32_t)c << 4) ^ (((uint32_t)r & 7) << 4)));
        cp16s(dst_base + off, src + (size_t)(rowbase + r) * ld + k0 + c * 8);
    }
}

template <int EPI>
__global__ __launch_bounds__(256, 1)
void tc_gemm(const __nv_bfloat16* __restrict__ Ah, const __nv_bfloat16* __restrict__ Al,
             const __nv_bfloat16* __restrict__ Bh, const __nv_bfloat16* __restrict__ Bl,
             float* __restrict__ Cf,
             __nv_bfloat16* __restrict__ Ch, __nv_bfloat16* __restrict__ Cl,
             int K, size_t lda, size_t ldb, size_t ldc,
             size_t sA, size_t sB, size_t sC, float scale)
{
    extern __shared__ char smem[];
    const uint32_t sbase = smem_u32(smem);
    const int tid = threadIdx.x;
    const int wid = tid >> 5, lane = tid & 31;
    const int wm = wid >> 1, wn = wid & 1;       // 4x2 warp grid; warp tile 32x64

    Ah += (size_t)blockIdx.z * sA;  Al += (size_t)blockIdx.z * sA;
    Bh += (size_t)blockIdx.z * sB;  Bl += (size_t)blockIdx.z * sB;
    if (EPI == 0) Cf += (size_t)blockIdx.z * sC;
    else        { Ch += (size_t)blockIdx.z * sC; Cl += (size_t)blockIdx.z * sC; }

    const int bm = blockIdx.y * 128;
    const int bn = blockIdx.x * 128;

    // per-lane ldmatrix address pieces
    const int grp = lane >> 3, wi = lane & 7;
    const uint32_t xw    = (uint32_t)wi << 4;                       // swizzle XOR
    const uint32_t aRow0 = (uint32_t)(wm * 32 + (grp & 1) * 8 + wi) * 128;
    const uint32_t aKsel = (uint32_t)(grp >> 1) << 4;
    const uint32_t bRow0 = (uint32_t)(wn * 64 + (grp >> 1) * 8 + wi) * 128;
    const uint32_t bKsel = (uint32_t)(grp & 1) << 4;

    float acc[2][8][4];
#pragma unroll
    for (int i = 0; i < 2; i++)
#pragma unroll
        for (int j = 0; j < 8; j++)
#pragma unroll
            for (int r = 0; r < 4; r++) acc[i][j][r] = 0.f;

    auto fill_stage = [&](int s, int kt) {
        const uint32_t st = sbase + (uint32_t)s * STAGE;
        const int k0 = kt * BKT;
        fill_sub(st,           Ah, lda, bm, k0, tid);
        fill_sub(st + SUB,     Al, lda, bm, k0, tid);
        fill_sub(st + 2 * SUB, Bh, ldb, bn, k0, tid);
        fill_sub(st + 3 * SUB, Bl, ldb, bn, k0, tid);
        cp_commit();
    };

    const int NT = K / BKT;
    fill_stage(0, 0);
    fill_stage(1, 1);

    for (int kt = 0; kt < NT; kt++) {
        if (kt + 2 < NT) { fill_stage((kt + 2) % STAGES, kt + 2); cp_wait<2>(); }
        else             { cp_wait<0>(); }
        __syncthreads();

        const uint32_t st = sbase + (uint32_t)(kt % STAGES) * STAGE;
#pragma unroll
        for (int kk = 0; kk < 4; kk++) {
            const uint32_t ak = ((uint32_t)(kk * 32) + aKsel) ^ xw;
            const uint32_t bk = ((uint32_t)(kk * 32) + bKsel) ^ xw;

            uint32_t ah[2][4], al[2][4];
#pragma unroll
            for (int mt = 0; mt < 2; mt++) {
                const uint32_t ao = aRow0 + (uint32_t)mt * 2048 + ak;
                ldsm4(ah[mt], st + ao);
                ldsm4(al[mt], st + SUB + ao);
            }
            uint32_t bh[4][4], bl[4][4];
#pragma unroll
            for (int np = 0; np < 4; np++) {
                const uint32_t bo = bRow0 + (uint32_t)np * 2048 + bk;
                ldsm4(bh[np], st + 2 * SUB + bo);
                ldsm4(bl[np], st + 3 * SUB + bo);
            }
#pragma unroll
            for (int mt = 0; mt < 2; mt++)
#pragma unroll
                for (int nt = 0; nt < 8; nt++) {
                    const int np = nt >> 1, h = (nt & 1) * 2;
                    mma_bf16(acc[mt][nt], ah[mt], bh[np][h], bh[np][h + 1]);
                    mma_bf16(acc[mt][nt], ah[mt], bl[np][h], bl[np][h + 1]);
                    mma_bf16(acc[mt][nt], al[mt], bh[np][h], bh[np][h + 1]);
                }
        }
        __syncthreads();
    }

    // epilogue
    const int g = lane >> 2, t = lane & 3;
#pragma unroll
    for (int mt = 0; mt < 2; mt++)
#pragma unroll
        for (int nt = 0; nt < 8; nt++) {
            const size_t row0 = (size_t)(bm + wm * 32 + mt * 16 + g);
            const size_t col  = (size_t)(bn + wn * 64 + nt * 8 + 2 * t);
            float d0 = acc[mt][nt][0] * scale, d1 = acc[mt][nt][1] * scale;
            float d2 = acc[mt][nt][2] * scale, d3 = acc[mt][nt][3] * scale;
            if (EPI == 0) {
                *(float2*)(Cf + row0 * ldc + col)       = make_float2(d0, d1);
                *(float2*)(Cf + (row0 + 8) * ldc + col) = make_float2(d2, d3);
            } else {
                __nv_bfloat16 h0, l0, h1, l1;
                split2(d0, h0, l0); split2(d1, h1, l1);
                *(__nv_bfloat162*)(Ch + row0 * ldc + col) = __halves2bfloat162(h0, h1);
                *(__nv_bfloat162*)(Cl + row0 * ldc + col) = __halves2bfloat162(l0, l1);
                split2(d2, h0, l0); split2(d3, h1, l1);
                *(__nv_bfloat162*)(Ch + (row0 + 8) * ldc + col) = __halves2bfloat162(h0, h1);
                *(__nv_bfloat162*)(Cl + (row0 + 8) * ldc + col) = __halves2bfloat162(l0, l1);
            }
        }
}

// ---------------------------------------------------------------------------
__global__ __launch_bounds__(256)
void split_kernel(const float* __restrict__ x, __nv_bfloat16* __restrict__ h,
                  __nv_bfloat16* __restrict__ l)
{
    const size_t i = (size_t)blockIdx.x * 256 + threadIdx.x;
    float4 v = ((const float4*)x)[i];
    __nv_bfloat16 h0, l0, h1, l1, h2, l2, h3, l3;
    split2(v.x, h0, l0); split2(v.y, h1, l1);
    split2(v.z, h2, l2); split2(v.w, h3, l3);
    __nv_bfloat162 ha = __halves2bfloat162(h0, h1), hb = __halves2bfloat162(h2, h3);
    __nv_bfloat162 la = __halves2bfloat162(l0, l1), lb = __halves2bfloat162(l2, l3);
    ((uint2*)h)[i] = make_uint2(*(uint32_t*)&ha, *(uint32_t*)&hb);
    ((uint2*)l)[i] = make_uint2(*(uint32_t*)&la, *(uint32_t*)&lb);
}

__global__ __launch_bounds__(256)
void softmax_kernel(const float* __restrict__ S, __nv_bfloat16* __restrict__ Ph,
                    __nv_bfloat16* __restrict__ Pl)
{
    const size_t row = blockIdx.x;
    const float* s = S + row * (size_t)S_;
    const int t = threadIdx.x;

    float vals[8];
    float local = 0.f;
#pragma unroll
    for (int i = 0; i < 8; i++) {
        float v = expf(s[t + i * 256]);
        vals[i] = v;
        local += v;
    }
    __shared__ float red[256];
    red[t] = local;
    __syncthreads();
#pragma unroll
    for (int off = 128; off > 0; off >>= 1) {
        if (t < off) red[t] += red[t + off];
        __syncthreads();
    }
    const float inv = 1.f / red[0];
    __nv_bfloat16* ph = Ph + row * (size_t)S_;
    __nv_bfloat16* pl = Pl + row * (size_t)S_;
#pragma unroll
    for (int i = 0; i < 8; i++) {
        __nv_bfloat16 h, l;
        split2(vals[i] * inv, h, l);
        ph[t + i * 256] = h;
        pl[t + i * 256] = l;
    }
}

// ---------------------------------------------------------------------------
extern "C" void kernel_launch(void* const* d_in, const int* in_sizes, int n_in,
                              void* d_out, int out_size)
{
    const float* q  = (const float*)d_in[0];
    const float* k  = (const float*)d_in[1];
    const float* v  = (const float*)d_in[2];
    const float* wq = (const float*)d_in[3];
    const float* wk = (const float*)d_in[4];
    const float* wv = (const float*)d_in[5];
    float* out = (float*)d_out;

    __nv_bfloat16 *qh, *ql, *kh, *kl, *vh, *vl;
    __nv_bfloat16 *wqh, *wql, *wkh, *wkl, *wvh, *wvl;
    __nv_bfloat16 *qph, *qpl, *kph, *kpl, *vth, *vtl, *pph, *ppl;
    float* sbuf;
    cudaGetSymbolAddress((void**)&qh, g_qh);   cudaGetSymbolAddress((void**)&ql, g_ql);
    cudaGetSymbolAddress((void**)&kh, g_kh);   cudaGetSymbolAddress((void**)&kl, g_kl);
    cudaGetSymbolAddress((void**)&vh, g_vh);   cudaGetSymbolAddress((void**)&vl, g_vl);
    cudaGetSymbolAddress((void**)&wqh, g_wqh); cudaGetSymbolAddress((void**)&wql, g_wql);
    cudaGetSymbolAddress((void**)&wkh, g_wkh); cudaGetSymbolAddress((void**)&wkl, g_wkl);
    cudaGetSymbolAddress((void**)&wvh, g_wvh); cudaGetSymbolAddress((void**)&wvl, g_wvl);
    cudaGetSymbolAddress((void**)&qph, g_qph); cudaGetSymbolAddress((void**)&qpl, g_qpl);
    cudaGetSymbolAddress((void**)&kph, g_kph); cudaGetSymbolAddress((void**)&kpl, g_kpl);
    cudaGetSymbolAddress((void**)&vth, g_vth); cudaGetSymbolAddress((void**)&vtl, g_vtl);
    cudaGetSymbolAddress((void**)&pph, g_ph);  cudaGetSymbolAddress((void**)&ppl, g_pl);
    cudaGetSymbolAddress((void**)&sbuf, g_s);

    cudaFuncSetAttribute(tc_gemm<0>, cudaFuncAttributeMaxDynamicSharedMemorySize, GEMM_SMEM);
    cudaFuncSetAttribute(tc_gemm<1>, cudaFuncAttributeMaxDynamicSharedMemorySize, GEMM_SMEM);

    // 1) split fp32 inputs -> bf16 hi/lo
    const size_t NQ = (size_t)MS_ * D_, NW = (size_t)D_ * D_;
    split_kernel<<<NQ / 1024, 256>>>(q, qh, ql);
    split_kernel<<<NQ / 1024, 256>>>(k, kh, kl);
    split_kernel<<<NQ / 1024, 256>>>(v, vh, vl);
    split_kernel<<<NW / 1024, 256>>>(wq, wqh, wql);
    split_kernel<<<NW / 1024, 256>>>(wk, wkh, wkl);
    split_kernel<<<NW / 1024, 256>>>(wv, wvh, wvl);

    // 2) projections (NT, K=1024)
    dim3 gq(D_ / 128, MS_ / 128, 1);
    tc_gemm<1><<<gq, 256, GEMM_SMEM>>>(qh, ql, wqh, wql, nullptr, qph, qpl,
                                       D_, D_, D_, D_, 0, 0, 0, 1.f);
    tc_gemm<1><<<gq, 256, GEMM_SMEM>>>(kh, kl, wkh, wkl, nullptr, kph, kpl,
                                       D_, D_, D_, D_, 0, 0, 0, 1.f);
    // vp^T = Wv @ v^T : M=1024, N=8192 (free transpose via role swap)
    dim3 gv(MS_ / 128, D_ / 128, 1);
    tc_gemm<1><<<gv, 256, GEMM_SMEM>>>(wvh, wvl, vh, vl, nullptr, vth, vtl,
                                       D_, D_, D_, MS_, 0, 0, 0, 1.f);

    // 3) scores s = qp kp^T / 32 (batched, M=N=2048, K=1024), fp32 out
    dim3 gs(S_ / 128, S_ / 128, B_);
    tc_gemm<0><<<gs, 256, GEMM_SMEM>>>(qph, qpl, kph, kpl, sbuf, nullptr, nullptr,
                                       D_, D_, D_, S_,
                                       (size_t)S_ * D_, (size_t)S_ * D_, (size_t)S_ * S_,
                                       1.f / 32.f);

    // 4) softmax rows -> P hi/lo
    softmax_kernel<<<B_ * S_, 256>>>(sbuf, pph, ppl);

    // 5) out = P @ vp (NT: B = vp^T rows, K-contig), M=2048, N=1024, K=2048
    dim3 go(D_ / 128, S_ / 128, B_);
    tc_gemm<0><<<go, 256, GEMM_SMEM>>>(pph, ppl, vth, vtl, out, nullptr, nullptr,
                                       S_, S_, MS_, D_,
                                       (size_t)S_ * S_, (size_t)S_, (size_t)S_ * D_,
                                       1.f);
}

// round 5
// speedup vs baseline: 1.0144x; 1.0144x over previous
#include <cuda_runtime.h>
#include <cuda_bf16.h>
#include <math.h>
#include <cstdint>

// ---------------------------------------------------------------------------
// AttentionHead B=4, S=2048, D=1024 — mma.sync bf16 split-precision (bf16x3).
// s = q (Wq^T Wk) k^T / 32  (kp projection eliminated via M' = Wk^T Wq).
// All GEMMs NT: C[m,n] = scale*sum_k (Ah+Al)[m,k]*(Bh+Bl)[n,k], lo*lo dropped.
// BK=32, hi/lo interleaved per 128B smem row, 3 stages = 96KB -> 2 CTAs/SM.
// ---------------------------------------------------------------------------

#define B_ 4
#define S_ 2048
#define D_ 1024
#define MS_ (B_ * S_)   // 8192

// ---- scratch (device globals) ----
__device__ __align__(16) __nv_bfloat16 g_qh [(size_t)MS_ * D_];
__device__ __align__(16) __nv_bfloat16 g_ql [(size_t)MS_ * D_];
__device__ __align__(16) __nv_bfloat16 g_kh [(size_t)MS_ * D_];
__device__ __align__(16) __nv_bfloat16 g_kl [(size_t)MS_ * D_];
__device__ __align__(16) __nv_bfloat16 g_vh [(size_t)MS_ * D_];
__device__ __align__(16) __nv_bfloat16 g_vl [(size_t)MS_ * D_];
__device__ __align__(16) __nv_bfloat16 g_wqth[(size_t)D_ * D_];  // Wq^T hi/lo
__device__ __align__(16) __nv_bfloat16 g_wqtl[(size_t)D_ * D_];
__device__ __align__(16) __nv_bfloat16 g_wkth[(size_t)D_ * D_];  // Wk^T hi/lo
__device__ __align__(16) __nv_bfloat16 g_wktl[(size_t)D_ * D_];
__device__ __align__(16) __nv_bfloat16 g_wvh [(size_t)D_ * D_];
__device__ __align__(16) __nv_bfloat16 g_wvl [(size_t)D_ * D_];
__device__ __align__(16) __nv_bfloat16 g_mh  [(size_t)D_ * D_];  // M'[e,d]
__device__ __align__(16) __nv_bfloat16 g_ml  [(size_t)D_ * D_];
__device__ __align__(16) __nv_bfloat16 g_qmh [(size_t)MS_ * D_]; // qM[i,e]
__device__ __align__(16) __nv_bfloat16 g_qml [(size_t)MS_ * D_];
__device__ __align__(16) __nv_bfloat16 g_vth [(size_t)D_ * MS_]; // vp^T [D, MS]
__device__ __align__(16) __nv_bfloat16 g_vtl [(size_t)D_ * MS_];
__device__ __align__(16) float         g_s   [(size_t)B_ * S_ * S_];
__device__ __align__(16) __nv_bfloat16 g_ph  [(size_t)B_ * S_ * S_];
__device__ __align__(16) __nv_bfloat16 g_pl  [(size_t)B_ * S_ * S_];

// ---- helpers ----
__device__ __forceinline__ uint32_t smem_u32(const void* p) {
    uint32_t a;
    asm("{ .reg .u64 t; cvta.to.shared.u64 t, %1; cvt.u32.u64 %0, t; }" : "=r"(a) : "l"(p));
    return a;
}
__device__ __forceinline__ void cp16s(uint32_t dst, const void* src) {
    asm volatile("cp.async.cg.shared.global [%0], [%1], 16;\n" :: "r"(dst), "l"(src));
}
__device__ __forceinline__ void cp_commit() { asm volatile("cp.async.commit_group;\n"); }
template <int N> __device__ __forceinline__ void cp_wait() {
    asm volatile("cp.async.wait_group %0;\n" :: "n"(N));
}
__device__ __forceinline__ void ldsm4(uint32_t (&r)[4], uint32_t addr) {
    asm volatile("ldmatrix.sync.aligned.m8n8.x4.shared.b16 {%0,%1,%2,%3}, [%4];"
                 : "=r"(r[0]), "=r"(r[1]), "=r"(r[2]), "=r"(r[3]) : "r"(addr));
}
__device__ __forceinline__ void mma_bf16(float (&d)[4], const uint32_t (&a)[4],
                                         uint32_t b0, uint32_t b1) {
    asm volatile(
        "mma.sync.aligned.m16n8k16.row.col.f32.bf16.bf16.f32 "
        "{%0,%1,%2,%3}, {%4,%5,%6,%7}, {%8,%9}, {%0,%1,%2,%3};\n"
        : "+f"(d[0]), "+f"(d[1]), "+f"(d[2]), "+f"(d[3])
        : "r"(a[0]), "r"(a[1]), "r"(a[2]), "r"(a[3]), "r"(b0), "r"(b1));
}
__device__ __forceinline__ void split2(float x, __nv_bfloat16& h, __nv_bfloat16& l) {
    h = __float2bfloat16_rn(x);
    l = __float2bfloat16_rn(x - __bfloat162float(h));
}

// ---------------------------------------------------------------------------
// GEMM: BM=BN=128, BK=32. Each smem row = 128B: [hi k0..31 | lo k0..31],
// SW128 XOR swizzle; lo fragment address = hi address ^ 64.
// 8 warps, warp tile 32x64. EPI 0 = fp32*scale, EPI 1 = bf16 hi/lo split.
// ---------------------------------------------------------------------------
constexpr int SUBT = 128 * 128;             // 16 KB per operand (A or B)
constexpr int STAGE = 2 * SUBT;             // 32 KB
constexpr int STAGES = 3;
constexpr int GEMM_SMEM = STAGES * STAGE;   // 98304 B -> 2 CTAs/SM

__device__ __forceinline__ void fill_sub(uint32_t dst_base,
                                         const __nv_bfloat16* __restrict__ H,
                                         const __nv_bfloat16* __restrict__ L,
                                         size_t ld, int rowbase, int k0, int tid) {
#pragma unroll
    for (int p = 0; p < 4; p++) {
        int idx = tid + p * 256;          // 0..1023 chunks
        int r = idx >> 3, c = idx & 7;    // row 0..127, 16B chunk 0..7
        uint32_t off = (uint32_t)(r * 128) + ((((uint32_t)c) ^ ((uint32_t)r & 7)) << 4);
        const __nv_bfloat16* src = (c < 4)
            ? H + (size_t)(rowbase + r) * ld + k0 + c * 8
            : L + (size_t)(rowbase + r) * ld + k0 + (c - 4) * 8;
        cp16s(dst_base + off, src);
    }
}

template <int EPI>
__global__ __launch_bounds__(256, 2)
void tc_gemm(const __nv_bfloat16* __restrict__ Ah, const __nv_bfloat16* __restrict__ Al,
             const __nv_bfloat16* __restrict__ Bh, const __nv_bfloat16* __restrict__ Bl,
             float* __restrict__ Cf,
             __nv_bfloat16* __restrict__ Ch, __nv_bfloat16* __restrict__ Cl,
             int K, size_t lda, size_t ldb, size_t ldc,
             size_t sA, size_t sB, size_t sC, float scale)
{
    extern __shared__ char smem[];
    const uint32_t sbase = smem_u32(smem);
    const int tid = threadIdx.x;
    const int wid = tid >> 5, lane = tid & 31;
    const int wm = wid >> 1, wn = wid & 1;       // 4x2 warp grid; warp tile 32x64

    Ah += (size_t)blockIdx.z * sA;  Al += (size_t)blockIdx.z * sA;
    Bh += (size_t)blockIdx.z * sB;  Bl += (size_t)blockIdx.z * sB;
    if (EPI == 0) Cf += (size_t)blockIdx.z * sC;
    else        { Ch += (size_t)blockIdx.z * sC; Cl += (size_t)blockIdx.z * sC; }

    const int bm = blockIdx.y * 128;
    const int bn = blockIdx.x * 128;

    const int grp = lane >> 3, wi = lane & 7;
    const uint32_t xw = (uint32_t)wi << 4;
    const uint32_t aRow = (uint32_t)(wm * 32 + (grp & 1) * 8 + wi) * 128;
    const uint32_t bRow = (uint32_t)(wn * 64 + (grp >> 1) * 8 + wi) * 128;

    float acc[2][8][4];
#pragma unroll
    for (int i = 0; i < 2; i++)
#pragma unroll
        for (int j = 0; j < 8; j++)
#pragma unroll
            for (int r = 0; r < 4; r++) acc[i][j][r] = 0.f;

    auto fill_stage = [&](int s, int kt) {
        const uint32_t st = sbase + (uint32_t)s * STAGE;
        const int k0 = kt * 32;
        fill_sub(st,        Ah, Al, lda, bm, k0, tid);
        fill_sub(st + SUBT, Bh, Bl, ldb, bn, k0, tid);
        cp_commit();
    };

    const int NT = K / 32;
    fill_stage(0, 0);
    fill_stage(1, 1);

    for (int kt = 0; kt < NT; kt++) {
        if (kt + 2 < NT) { fill_stage((kt + 2) % STAGES, kt + 2); cp_wait<2>(); }
        else             { cp_wait<0>(); }
        __syncthreads();

        const uint32_t st = sbase + (uint32_t)(kt % STAGES) * STAGE;
#pragma unroll
        for (int kk = 0; kk < 2; kk++) {
            // A fragments (hi+lo): chunk = kk*2 + (grp>>1) in 0..3; lo = hi^64
            uint32_t ah[2][4], al[2][4];
            const uint32_t ak = ((uint32_t)(kk * 2 + (grp >> 1)) << 4) ^ xw;
#pragma unroll
            for (int mt = 0; mt < 2; mt++) {
                const uint32_t ao = st + aRow + (uint32_t)mt * 2048 + ak;
                ldsm4(ah[mt], ao);
                ldsm4(al[mt], ao ^ 64u);
            }
            const uint32_t bk = ((uint32_t)(kk * 2 + (grp & 1)) << 4) ^ xw;
#pragma unroll
            for (int np = 0; np < 4; np++) {
                uint32_t bh[4], bl[4];
                const uint32_t bo = st + SUBT + bRow + (uint32_t)np * 2048 + bk;
                ldsm4(bh, bo);
                ldsm4(bl, bo ^ 64u);
#pragma unroll
                for (int mt = 0; mt < 2; mt++) {
#pragma unroll
                    for (int half = 0; half < 2; half++) {
                        const int nt = np * 2 + half;
                        const int h = half * 2;
                        mma_bf16(acc[mt][nt], ah[mt], bh[h], bh[h + 1]);
                        mma_bf16(acc[mt][nt], ah[mt], bl[h], bl[h + 1]);
                        mma_bf16(acc[mt][nt], al[mt], bh[h], bh[h + 1]);
                    }
                }
            }
        }
        __syncthreads();
    }

    // epilogue
    const int g = lane >> 2, t = lane & 3;
#pragma unroll
    for (int mt = 0; mt < 2; mt++)
#pragma unroll
        for (int nt = 0; nt < 8; nt++) {
            const size_t row0 = (size_t)(bm + wm * 32 + mt * 16 + g);
            const size_t col  = (size_t)(bn + wn * 64 + nt * 8 + 2 * t);
            float d0 = acc[mt][nt][0] * scale, d1 = acc[mt][nt][1] * scale;
            float d2 = acc[mt][nt][2] * scale, d3 = acc[mt][nt][3] * scale;
            if (EPI == 0) {
                *(float2*)(Cf + row0 * ldc + col)       = make_float2(d0, d1);
                *(float2*)(Cf + (row0 + 8) * ldc + col) = make_float2(d2, d3);
            } else {
                __nv_bfloat16 h0, l0, h1, l1;
                split2(d0, h0, l0); split2(d1, h1, l1);
                *(__nv_bfloat162*)(Ch + row0 * ldc + col) = __halves2bfloat162(h0, h1);
                *(__nv_bfloat162*)(Cl + row0 * ldc + col) = __halves2bfloat162(l0, l1);
                split2(d2, h0, l0); split2(d3, h1, l1);
                *(__nv_bfloat162*)(Ch + (row0 + 8) * ldc + col) = __halves2bfloat162(h0, h1);
                *(__nv_bfloat162*)(Cl + (row0 + 8) * ldc + col) = __halves2bfloat162(l0, l1);
            }
        }
}

// ---------------------------------------------------------------------------
__global__ __launch_bounds__(256)
void split_kernel(const float* __restrict__ x, __nv_bfloat16* __restrict__ h,
                  __nv_bfloat16* __restrict__ l)
{
    const size_t i = (size_t)blockIdx.x * 256 + threadIdx.x;
    float4 v = ((const float4*)x)[i];
    __nv_bfloat16 h0, l0, h1, l1, h2, l2, h3, l3;
    split2(v.x, h0, l0); split2(v.y, h1, l1);
    split2(v.z, h2, l2); split2(v.w, h3, l3);
    __nv_bfloat162 ha = __halves2bfloat162(h0, h1), hb = __halves2bfloat162(h2, h3);
    __nv_bfloat162 la = __halves2bfloat162(l0, l1), lb = __halves2bfloat162(l2, l3);
    ((uint2*)h)[i] = make_uint2(*(uint32_t*)&ha, *(uint32_t*)&hb);
    ((uint2*)l)[i] = make_uint2(*(uint32_t*)&la, *(uint32_t*)&lb);
}

// transpose + split: W [1024,1024] fp32 -> W^T hi/lo bf16 [1024,1024]
__global__ __launch_bounds__(256)
void splitT_kernel(const float* __restrict__ x, __nv_bfloat16* __restrict__ h,
                   __nv_bfloat16* __restrict__ l)
{
    __shared__ float tile[32][33];
    const int tx = threadIdx.x & 31, ty = threadIdx.x >> 5;  // 32 x 8
    const int r0 = blockIdx.y * 32, c0 = blockIdx.x * 32;
#pragma unroll
    for (int i = 0; i < 4; i++)
        tile[ty + i * 8][tx] = x[(size_t)(r0 + ty + i * 8) * D_ + c0 + tx];
    __syncthreads();
#pragma unroll
    for (int i = 0; i < 4; i++) {
        float v = tile[tx][ty + i * 8];
        __nv_bfloat16 hh, ll;
        split2(v, hh, ll);
        h[(size_t)(c0 + ty + i * 8) * D_ + r0 + tx] = hh;
        l[(size_t)(c0 + ty + i * 8) * D_ + r0 + tx] = ll;
    }
}

__global__ __launch_bounds__(256)
void softmax_kernel(const float* __restrict__ S, __nv_bfloat16* __restrict__ Ph,
                    __nv_bfloat16* __restrict__ Pl)
{
    const size_t row = blockIdx.x;
    const float* s = S + row * (size_t)S_;
    const int t = threadIdx.x;

    float vals[8];
    float local = 0.f;
#pragma unroll
    for (int i = 0; i < 8; i++) {
        float v = expf(s[t + i * 256]);
        vals[i] = v;
        local += v;
    }
    __shared__ float red[256];
    red[t] = local;
    __syncthreads();
#pragma unroll
    for (int off = 128; off > 0; off >>= 1) {
        if (t < off) red[t] += red[t + off];
        __syncthreads();
    }
    const float inv = 1.f / red[0];
    __nv_bfloat16* ph = Ph + row * (size_t)S_;
    __nv_bfloat16* pl = Pl + row * (size_t)S_;
#pragma unroll
    for (int i = 0; i < 8; i++) {
        __nv_bfloat16 h, l;
        split2(vals[i] * inv, h, l);
        ph[t + i * 256] = h;
        pl[t + i * 256] = l;
    }
}

// ---------------------------------------------------------------------------
extern "C" void kernel_launch(void* const* d_in, const int* in_sizes, int n_in,
                              void* d_out, int out_size)
{
    const float* q  = (const float*)d_in[0];
    const float* k  = (const float*)d_in[1];
    const float* v  = (const float*)d_in[2];
    const float* wq = (const float*)d_in[3];
    const float* wk = (const float*)d_in[4];
    const float* wv = (const float*)d_in[5];
    float* out = (float*)d_out;

    __nv_bfloat16 *qh, *ql, *kh, *kl, *vh, *vl;
    __nv_bfloat16 *wqth, *wqtl, *wkth, *wktl, *wvh, *wvl;
    __nv_bfloat16 *mh, *ml, *qmh, *qml, *vth, *vtl, *pph, *ppl;
    float* sbuf;
    cudaGetSymbolAddress((void**)&qh, g_qh);     cudaGetSymbolAddress((void**)&ql, g_ql);
    cudaGetSymbolAddress((void**)&kh, g_kh);     cudaGetSymbolAddress((void**)&kl, g_kl);
    cudaGetSymbolAddress((void**)&vh, g_vh);     cudaGetSymbolAddress((void**)&vl, g_vl);
    cudaGetSymbolAddress((void**)&wqth, g_wqth); cudaGetSymbolAddress((void**)&wqtl, g_wqtl);
    cudaGetSymbolAddress((void**)&wkth, g_wkth); cudaGetSymbolAddress((void**)&wktl, g_wktl);
    cudaGetSymbolAddress((void**)&wvh, g_wvh);   cudaGetSymbolAddress((void**)&wvl, g_wvl);
    cudaGetSymbolAddress((void**)&mh, g_mh);     cudaGetSymbolAddress((void**)&ml, g_ml);
    cudaGetSymbolAddress((void**)&qmh, g_qmh);   cudaGetSymbolAddress((void**)&qml, g_qml);
    cudaGetSymbolAddress((void**)&vth, g_vth);   cudaGetSymbolAddress((void**)&vtl, g_vtl);
    cudaGetSymbolAddress((void**)&pph, g_ph);    cudaGetSymbolAddress((void**)&ppl, g_pl);
    cudaGetSymbolAddress((void**)&sbuf, g_s);

    cudaFuncSetAttribute(tc_gemm<0>, cudaFuncAttributeMaxDynamicSharedMemorySize, GEMM_SMEM);
    cudaFuncSetAttribute(tc_gemm<1>, cudaFuncAttributeMaxDynamicSharedMemorySize, GEMM_SMEM);

    // 1) splits: q,k,v,wv plain; wq,wk transposed
    const size_t NQ = (size_t)MS_ * D_, NW = (size_t)D_ * D_;
    split_kernel<<<NQ / 1024, 256>>>(q, qh, ql);
    split_kernel<<<NQ / 1024, 256>>>(k, kh, kl);
    split_kernel<<<NQ / 1024, 256>>>(v, vh, vl);
    split_kernel<<<NW / 1024, 256>>>(wv, wvh, wvl);
    dim3 gt(32, 32);
    splitT_kernel<<<gt, 256>>>(wq, wqth, wqtl);
    splitT_kernel<<<gt, 256>>>(wk, wkth, wktl);

    // 2) M'[e,d] = sum_o Wk[o,e]*Wq[o,d]  (NT on transposed weights), K=1024
    dim3 gm(D_ / 128, D_ / 128, 1);
    tc_gemm<1><<<gm, 256, GEMM_SMEM>>>(wkth, wktl, wqth, wqtl, nullptr, mh, ml,
                                       D_, D_, D_, D_, 0, 0, 0, 1.f);

    // 3) qM[i,e] = sum_d q[i,d]*M'[e,d], M=8192, N=1024, K=1024
    dim3 gq(D_ / 128, MS_ / 128, 1);
    tc_gemm<1><<<gq, 256, GEMM_SMEM>>>(qh, ql, mh, ml, nullptr, qmh, qml,
                                       D_, D_, D_, D_, 0, 0, 0, 1.f);

    // 4) vp^T[e,i] = sum_d Wv[e,d]*v[i,d], M=1024, N=8192, K=1024
    dim3 gv(MS_ / 128, D_ / 128, 1);
    tc_gemm<1><<<gv, 256, GEMM_SMEM>>>(wvh, wvl, vh, vl, nullptr, vth, vtl,
                                       D_, D_, D_, MS_, 0, 0, 0, 1.f);

    // 5) scores s[i,j] = sum_e qM[i,e]*k[j,e] / 32 (batched), K=1024
    dim3 gs(S_ / 128, S_ / 128, B_);
    tc_gemm<0><<<gs, 256, GEMM_SMEM>>>(qmh, qml, kh, kl, sbuf, nullptr, nullptr,
                                       D_, D_, D_, S_,
                                       (size_t)S_ * D_, (size_t)S_ * D_, (size_t)S_ * S_,
                                       1.f / 32.f);

    // 6) softmax rows -> P hi/lo
    softmax_kernel<<<B_ * S_, 256>>>(sbuf, pph, ppl);

    // 7) out = P @ vp (NT vs vp^T), M=2048, N=1024, K=2048 (batched)
    dim3 go(D_ / 128, S_ / 128, B_);
    tc_gemm<0><<<go, 256, GEMM_SMEM>>>(pph, ppl, vth, vtl, out, nullptr, nullptr,
                                       S_, S_, MS_, D_,
                                       (size_t)S_ * S_, (size_t)S_, (size_t)S_ * D_,
                                       1.f);
}

// round 6
// speedup vs baseline: 1.2018x; 1.1848x over previous
#include <cuda_runtime.h>
#include <cuda_bf16.h>
#include <math.h>
#include <cstdint>

// ---------------------------------------------------------------------------
// AttentionHead B=4, S=2048, D=1024 — mma.sync bf16 split-precision (bf16x3).
// s = q (Wk^T Wq applied as M') k^T / 32 ; softmax fused into scores epilogue
// (exp + split + deterministic row-partials) and PV epilogue (1/rowsum scale).
// ---------------------------------------------------------------------------

#define B_ 4
#define S_ 2048
#define D_ 1024
#define MS_ (B_ * S_)   // 8192
typedef __nv_bfloat16 bf;

// ---- scratch ----
__device__ __align__(16) bf g_qh [(size_t)MS_ * D_];
__device__ __align__(16) bf g_ql [(size_t)MS_ * D_];
__device__ __align__(16) bf g_kh [(size_t)MS_ * D_];
__device__ __align__(16) bf g_kl [(size_t)MS_ * D_];
__device__ __align__(16) bf g_vh [(size_t)MS_ * D_];
__device__ __align__(16) bf g_vl [(size_t)MS_ * D_];
__device__ __align__(16) bf g_wqth[(size_t)D_ * D_];
__device__ __align__(16) bf g_wqtl[(size_t)D_ * D_];
__device__ __align__(16) bf g_wkth[(size_t)D_ * D_];
__device__ __align__(16) bf g_wktl[(size_t)D_ * D_];
__device__ __align__(16) bf g_wvh [(size_t)D_ * D_];
__device__ __align__(16) bf g_wvl [(size_t)D_ * D_];
__device__ __align__(16) bf g_mh  [(size_t)D_ * D_];
__device__ __align__(16) bf g_ml  [(size_t)D_ * D_];
__device__ __align__(16) bf g_qmh [(size_t)MS_ * D_];
__device__ __align__(16) bf g_qml [(size_t)MS_ * D_];
__device__ __align__(16) bf g_vth [(size_t)D_ * MS_];
__device__ __align__(16) bf g_vtl [(size_t)D_ * MS_];
__device__ __align__(16) bf g_eh  [(size_t)B_ * S_ * S_];
__device__ __align__(16) bf g_el  [(size_t)B_ * S_ * S_];
__device__ __align__(16) float g_part [(size_t)MS_ * 32];
__device__ __align__(16) float g_invrs[(size_t)MS_];

// ---- helpers ----
__device__ __forceinline__ uint32_t smem_u32(const void* p) {
    uint32_t a;
    asm("{ .reg .u64 t; cvta.to.shared.u64 t, %1; cvt.u32.u64 %0, t; }" : "=r"(a) : "l"(p));
    return a;
}
__device__ __forceinline__ void cp16s(uint32_t dst, const void* src) {
    asm volatile("cp.async.cg.shared.global [%0], [%1], 16;\n" :: "r"(dst), "l"(src));
}
__device__ __forceinline__ void cp_commit() { asm volatile("cp.async.commit_group;\n"); }
template <int N> __device__ __forceinline__ void cp_wait() {
    asm volatile("cp.async.wait_group %0;\n" :: "n"(N));
}
__device__ __forceinline__ void ldsm4(uint32_t (&r)[4], uint32_t addr) {
    asm volatile("ldmatrix.sync.aligned.m8n8.x4.shared.b16 {%0,%1,%2,%3}, [%4];"
                 : "=r"(r[0]), "=r"(r[1]), "=r"(r[2]), "=r"(r[3]) : "r"(addr));
}
__device__ __forceinline__ void mma_bf16(float (&d)[4], const uint32_t (&a)[4],
                                         uint32_t b0, uint32_t b1) {
    asm volatile(
        "mma.sync.aligned.m16n8k16.row.col.f32.bf16.bf16.f32 "
        "{%0,%1,%2,%3}, {%4,%5,%6,%7}, {%8,%9}, {%0,%1,%2,%3};\n"
        : "+f"(d[0]), "+f"(d[1]), "+f"(d[2]), "+f"(d[3])
        : "r"(a[0]), "r"(a[1]), "r"(a[2]), "r"(a[3]), "r"(b0), "r"(b1));
}
__device__ __forceinline__ void split2(float x, bf& h, bf& l) {
    h = __float2bfloat16_rn(x);
    l = __float2bfloat16_rn(x - __bfloat162float(h));
}

// ---------------------------------------------------------------------------
// 128x128 GEMM body, BK=32, hi/lo interleaved per 128B row, 3 stages (96KB).
// EPI 1: split C -> Ch/Cl.  EPI 2: e=exp(acc*scale) -> Ch/Cl + row partials.
// EPI 3: fp32 out scaled by invrs[row].
// ---------------------------------------------------------------------------
constexpr int SUBT = 128 * 128;             // 16 KB
constexpr int STAGE128 = 2 * SUBT;          // 32 KB
constexpr int GSMEM128 = 3 * STAGE128;      // 96 KB

__device__ __forceinline__ void fill128(uint32_t dst, const bf* __restrict__ H,
                                        const bf* __restrict__ L,
                                        size_t ld, int rowbase, int k0, int tid) {
#pragma unroll
    for (int p = 0; p < 4; p++) {
        int idx = tid + p * 256;
        int r = idx >> 3, c = idx & 7;
        uint32_t off = (uint32_t)(r * 128) + ((((uint32_t)c) ^ ((uint32_t)r & 7)) << 4);
        const bf* src = (c < 4)
            ? H + (size_t)(rowbase + r) * ld + k0 + c * 8
            : L + (size_t)(rowbase + r) * ld + k0 + (c - 4) * 8;
        cp16s(dst + off, src);
    }
}

template <int EPI>
__device__ __forceinline__ void gemm128_body(
    char* smem,
    const bf* __restrict__ Ah, const bf* __restrict__ Al,
    const bf* __restrict__ Bh, const bf* __restrict__ Bl,
    float* __restrict__ Cf, bf* __restrict__ Ch, bf* __restrict__ Cl,
    float* __restrict__ part, const float* __restrict__ invrs,
    int K, size_t lda, size_t ldb, size_t ldc,
    int bm, int bn, int bx, float scale)
{
    const uint32_t sbase = smem_u32(smem);
    const int tid = threadIdx.x;
    const int wid = tid >> 5, lane = tid & 31;
    const int wm = wid >> 1, wn = wid & 1;
    const int grp = lane >> 3, wi = lane & 7;
    const uint32_t xw = (uint32_t)wi << 4;
    const uint32_t aRow = (uint32_t)(wm * 32 + (grp & 1) * 8 + wi) * 128;
    const uint32_t bRow = (uint32_t)(wn * 64 + (grp >> 1) * 8 + wi) * 128;

    float acc[2][8][4];
#pragma unroll
    for (int i = 0; i < 2; i++)
#pragma unroll
        for (int j = 0; j < 8; j++)
#pragma unroll
            for (int r = 0; r < 4; r++) acc[i][j][r] = 0.f;

    auto fill_stage = [&](int s, int kt) {
        const uint32_t st = sbase + (uint32_t)s * STAGE128;
        fill128(st,        Ah, Al, lda, bm, kt * 32, tid);
        fill128(st + SUBT, Bh, Bl, ldb, bn, kt * 32, tid);
        cp_commit();
    };

    const int NT = K / 32;
    fill_stage(0, 0);
    fill_stage(1, 1);

    for (int kt = 0; kt < NT; kt++) {
        if (kt + 1 < NT) cp_wait<1>(); else cp_wait<0>();
        __syncthreads();
        if (kt + 2 < NT) fill_stage((kt + 2) % 3, kt + 2);

        const uint32_t st = sbase + (uint32_t)(kt % 3) * STAGE128;
#pragma unroll
        for (int kk = 0; kk < 2; kk++) {
            uint32_t ah[2][4], al[2][4];
            const uint32_t ak = ((uint32_t)(kk * 2 + (grp >> 1)) << 4) ^ xw;
#pragma unroll
            for (int mt = 0; mt < 2; mt++) {
                const uint32_t ao = st + aRow + (uint32_t)mt * 2048 + ak;
                ldsm4(ah[mt], ao);
                ldsm4(al[mt], ao ^ 64u);
            }
            const uint32_t bk = ((uint32_t)(kk * 2 + (grp & 1)) << 4) ^ xw;
            uint32_t bh[2][4], bl[2][4];
            {
                const uint32_t bo = st + SUBT + bRow + bk;
                ldsm4(bh[0], bo);
                ldsm4(bl[0], bo ^ 64u);
            }
#pragma unroll
            for (int np = 0; np < 4; np++) {
                const int cur = np & 1;
                if (np < 3) {
                    const uint32_t bo = st + SUBT + bRow + (uint32_t)(np + 1) * 2048 + bk;
                    ldsm4(bh[cur ^ 1], bo);
                    ldsm4(bl[cur ^ 1], bo ^ 64u);
                }
#pragma unroll
                for (int mt = 0; mt < 2; mt++) {
#pragma unroll
                    for (int half = 0; half < 2; half++) {
                        const int nt = np * 2 + half;
                        const int h = half * 2;
                        mma_bf16(acc[mt][nt], ah[mt], bh[cur][h], bh[cur][h + 1]);
                        mma_bf16(acc[mt][nt], ah[mt], bl[cur][h], bl[cur][h + 1]);
                        mma_bf16(acc[mt][nt], al[mt], bh[cur][h], bh[cur][h + 1]);
                    }
                }
            }
        }
    }

    const int g = lane >> 2, t = lane & 3;
#pragma unroll
    for (int mt = 0; mt < 2; mt++) {
        float p0 = 0.f, p1 = 0.f;
#pragma unroll
        for (int nt = 0; nt < 8; nt++) {
            const size_t row0 = (size_t)(bm + wm * 32 + mt * 16 + g);
            const size_t col  = (size_t)(bn + wn * 64 + nt * 8 + 2 * t);
            float d0 = acc[mt][nt][0], d1 = acc[mt][nt][1];
            float d2 = acc[mt][nt][2], d3 = acc[mt][nt][3];
            if (EPI == 1) {
                bf h0, l0, h1, l1;
                split2(d0, h0, l0); split2(d1, h1, l1);
                *(__nv_bfloat162*)(Ch + row0 * ldc + col) = __halves2bfloat162(h0, h1);
                *(__nv_bfloat162*)(Cl + row0 * ldc + col) = __halves2bfloat162(l0, l1);
                split2(d2, h0, l0); split2(d3, h1, l1);
                *(__nv_bfloat162*)(Ch + (row0 + 8) * ldc + col) = __halves2bfloat162(h0, h1);
                *(__nv_bfloat162*)(Cl + (row0 + 8) * ldc + col) = __halves2bfloat162(l0, l1);
            } else if (EPI == 2) {
                float e0 = __expf(d0 * scale), e1 = __expf(d1 * scale);
                float e2 = __expf(d2 * scale), e3 = __expf(d3 * scale);
                p0 += e0 + e1; p1 += e2 + e3;
                bf h0, l0, h1, l1;
                split2(e0, h0, l0); split2(e1, h1, l1);
                *(__nv_bfloat162*)(Ch + row0 * ldc + col) = __halves2bfloat162(h0, h1);
                *(__nv_bfloat162*)(Cl + row0 * ldc + col) = __halves2bfloat162(l0, l1);
                split2(e2, h0, l0); split2(e3, h1, l1);
                *(__nv_bfloat162*)(Ch + (row0 + 8) * ldc + col) = __halves2bfloat162(h0, h1);
                *(__nv_bfloat162*)(Cl + (row0 + 8) * ldc + col) = __halves2bfloat162(l0, l1);
            } else { // EPI == 3
                const float i0 = invrs[row0], i1 = invrs[row0 + 8];
                *(float2*)(Cf + row0 * ldc + col)       = make_float2(d0 * i0, d1 * i0);
                *(float2*)(Cf + (row0 + 8) * ldc + col) = make_float2(d2 * i1, d3 * i1);
            }
        }
        if (EPI == 2) {
            p0 += __shfl_xor_sync(0xffffffffu, p0, 1);
            p0 += __shfl_xor_sync(0xffffffffu, p0, 2);
            p1 += __shfl_xor_sync(0xffffffffu, p1, 1);
            p1 += __shfl_xor_sync(0xffffffffu, p1, 2);
            if (t == 0) {
                const int row0 = bm + wm * 32 + mt * 16 + g;
                part[(size_t)row0 * 32 + bx * 2 + wn]       = p0;
                part[(size_t)(row0 + 8) * 32 + bx * 2 + wn] = p1;
            }
        }
    }
}

// ---------------------------------------------------------------------------
// 64x64 GEMM (for M'), BK=32, 3 stages (48KB), EPI=1.
// ---------------------------------------------------------------------------
constexpr int SUB64 = 64 * 128;             // 8 KB
constexpr int STAGE64 = 2 * SUB64;          // 16 KB
constexpr int GSMEM64 = 3 * STAGE64;        // 48 KB

__device__ __forceinline__ void fill64(uint32_t dst, const bf* __restrict__ H,
                                       const bf* __restrict__ L,
                                       size_t ld, int rowbase, int k0, int tid) {
#pragma unroll
    for (int p = 0; p < 2; p++) {
        int idx = tid + p * 256;
        int r = idx >> 3, c = idx & 7;
        uint32_t off = (uint32_t)(r * 128) + ((((uint32_t)c) ^ ((uint32_t)r & 7)) << 4);
        const bf* src = (c < 4)
            ? H + (size_t)(rowbase + r) * ld + k0 + c * 8
            : L + (size_t)(rowbase + r) * ld + k0 + (c - 4) * 8;
        cp16s(dst + off, src);
    }
}

__device__ __forceinline__ void gemm64_body(
    char* smem,
    const bf* __restrict__ Ah, const bf* __restrict__ Al,
    const bf* __restrict__ Bh, const bf* __restrict__ Bl,
    bf* __restrict__ Ch, bf* __restrict__ Cl,
    int K, size_t ld, int bm, int bn)
{
    const uint32_t sbase = smem_u32(smem);
    const int tid = threadIdx.x;
    const int wid = tid >> 5, lane = tid & 31;
    const int wm = wid >> 1, wn = wid & 1;
    const int grp = lane >> 3, wi = lane & 7;
    const uint32_t xw = (uint32_t)wi << 4;
    const uint32_t aRow = (uint32_t)(wm * 16 + (grp & 1) * 8 + wi) * 128;
    const uint32_t bRow = (uint32_t)(wn * 32 + (grp >> 1) * 8 + wi) * 128;

    float acc[4][4];
#pragma unroll
    for (int j = 0; j < 4; j++)
#pragma unroll
        for (int r = 0; r < 4; r++) acc[j][r] = 0.f;

    auto fill_stage = [&](int s, int kt) {
        const uint32_t st = sbase + (uint32_t)s * STAGE64;
        fill64(st,         Ah, Al, ld, bm, kt * 32, tid);
        fill64(st + SUB64, Bh, Bl, ld, bn, kt * 32, tid);
        cp_commit();
    };

    const int NT = K / 32;
    fill_stage(0, 0);
    fill_stage(1, 1);

    for (int kt = 0; kt < NT; kt++) {
        if (kt + 1 < NT) cp_wait<1>(); else cp_wait<0>();
        __syncthreads();
        if (kt + 2 < NT) fill_stage((kt + 2) % 3, kt + 2);

        const uint32_t st = sbase + (uint32_t)(kt % 3) * STAGE64;
#pragma unroll
        for (int kk = 0; kk < 2; kk++) {
            uint32_t ah[4], al[4];
            const uint32_t ak = ((uint32_t)(kk * 2 + (grp >> 1)) << 4) ^ xw;
            const uint32_t ao = st + aRow + ak;
            ldsm4(ah, ao);
            ldsm4(al, ao ^ 64u);
            const uint32_t bk = ((uint32_t)(kk * 2 + (grp & 1)) << 4) ^ xw;
#pragma unroll
            for (int np = 0; np < 2; np++) {
                uint32_t bh[4], bl[4];
                const uint32_t bo = st + SUB64 + bRow + (uint32_t)np * 2048 + bk;
                ldsm4(bh, bo);
                ldsm4(bl, bo ^ 64u);
#pragma unroll
                for (int half = 0; half < 2; half++) {
                    const int nt = np * 2 + half;
                    const int h = half * 2;
                    mma_bf16(acc[nt], ah, bh[h], bh[h + 1]);
                    mma_bf16(acc[nt], ah, bl[h], bl[h + 1]);
                    mma_bf16(acc[nt], al, bh[h], bh[h + 1]);
                }
            }
        }
    }

    const int g = lane >> 2, t = lane & 3;
#pragma unroll
    for (int nt = 0; nt < 4; nt++) {
        const size_t row0 = (size_t)(bm + wm * 16 + g);
        const size_t col  = (size_t)(bn + wn * 32 + nt * 8 + 2 * t);
        bf h0, l0, h1, l1;
        split2(acc[nt][0], h0, l0); split2(acc[nt][1], h1, l1);
        *(__nv_bfloat162*)(Ch + row0 * ld + col) = __halves2bfloat162(h0, h1);
        *(__nv_bfloat162*)(Cl + row0 * ld + col) = __halves2bfloat162(l0, l1);
        split2(acc[nt][2], h0, l0); split2(acc[nt][3], h1, l1);
        *(__nv_bfloat162*)(Ch + (row0 + 8) * ld + col) = __halves2bfloat162(h0, h1);
        *(__nv_bfloat162*)(Cl + (row0 + 8) * ld + col) = __halves2bfloat162(l0, l1);
    }
}

// ---------------------------------------------------------------------------
// prep1: transpose+split wq, wk
// ---------------------------------------------------------------------------
__global__ __launch_bounds__(256)
void prep1_kernel(const float* __restrict__ wq, bf* __restrict__ wqth, bf* __restrict__ wqtl,
                  const float* __restrict__ wk, bf* __restrict__ wkth, bf* __restrict__ wktl)
{
    __shared__ float tile[32][33];
    const int tb = blockIdx.x & 1023;
    const float* x = (blockIdx.x < 1024) ? wq : wk;
    bf* h = (blockIdx.x < 1024) ? wqth : wkth;
    bf* l = (blockIdx.x < 1024) ? wqtl : wktl;
    const int tx = threadIdx.x & 31, ty = threadIdx.x >> 5;
    const int r0 = (tb >> 5) * 32, c0 = (tb & 31) * 32;
#pragma unroll
    for (int i = 0; i < 4; i++)
        tile[ty + i * 8][tx] = x[(size_t)(r0 + ty + i * 8) * D_ + c0 + tx];
    __syncthreads();
#pragma unroll
    for (int i = 0; i < 4; i++) {
        float vv = tile[tx][ty + i * 8];
        bf hh, ll;
        split2(vv, hh, ll);
        h[(size_t)(c0 + ty + i * 8) * D_ + r0 + tx] = hh;
        l[(size_t)(c0 + ty + i * 8) * D_ + r0 + tx] = ll;
    }
}

// ---------------------------------------------------------------------------
// prep2: blocks [0,256): M' 64x64 GEMM; [256,...): splits of q,k,v,wv.
// Each split block handles 2048 float4 = 8192 elements.
// ---------------------------------------------------------------------------
__device__ __forceinline__ void split_block(const float* __restrict__ x,
                                            bf* __restrict__ h, bf* __restrict__ l,
                                            size_t bi) {
    const float4* x4 = (const float4*)x;
    uint2* h2 = (uint2*)h;
    uint2* l2 = (uint2*)l;
    const size_t base = bi * 2048 + threadIdx.x;
#pragma unroll
    for (int j = 0; j < 8; j++) {
        float4 vv = x4[base + j * 256];
        bf h0, l0, h1, l1, h2b, l2b, h3, l3;
        split2(vv.x, h0, l0); split2(vv.y, h1, l1);
        split2(vv.z, h2b, l2b); split2(vv.w, h3, l3);
        __nv_bfloat162 ha = __halves2bfloat162(h0, h1), hb = __halves2bfloat162(h2b, h3);
        __nv_bfloat162 la = __halves2bfloat162(l0, l1), lb = __halves2bfloat162(l2b, l3);
        h2[base + j * 256] = make_uint2(*(uint32_t*)&ha, *(uint32_t*)&hb);
        l2[base + j * 256] = make_uint2(*(uint32_t*)&la, *(uint32_t*)&lb);
    }
}

__global__ __launch_bounds__(256, 2)
void prep2_kernel(const bf* __restrict__ wkth, const bf* __restrict__ wktl,
                  const bf* __restrict__ wqth, const bf* __restrict__ wqtl,
                  bf* __restrict__ mh, bf* __restrict__ ml,
                  const float* __restrict__ q, bf* __restrict__ qh, bf* __restrict__ ql,
                  const float* __restrict__ k, bf* __restrict__ kh, bf* __restrict__ kl,
                  const float* __restrict__ v, bf* __restrict__ vh, bf* __restrict__ vl,
                  const float* __restrict__ wv, bf* __restrict__ wvh, bf* __restrict__ wvl)
{
    extern __shared__ char smem[];
    const int bx = blockIdx.x;
    if (bx < 256) {
        // M'[e,d] = sum_o WkT[e,o] * WqT[d,o]
        gemm64_body(smem, wkth, wktl, wqth, wqtl, mh, ml,
                    D_, D_, (bx >> 4) * 64, (bx & 15) * 64);
    } else {
        int b = bx - 256;
        if (b < 1024)       split_block(q,  qh,  ql,  (size_t)b);
        else if (b < 2048)  split_block(k,  kh,  kl,  (size_t)(b - 1024));
        else if (b < 3072)  split_block(v,  vh,  vl,  (size_t)(b - 2048));
        else                split_block(wv, wvh, wvl, (size_t)(b - 3072));
    }
}

// ---------------------------------------------------------------------------
// dualproj: qM (512 blocks) + vp^T (512 blocks)
// ---------------------------------------------------------------------------
__global__ __launch_bounds__(256, 2)
void dualproj_kernel(const bf* qh, const bf* ql, const bf* mh, const bf* ml,
                     bf* qmh, bf* qml,
                     const bf* wvh, const bf* wvl, const bf* vh, const bf* vl,
                     bf* vth, bf* vtl)
{
    extern __shared__ char smem[];
    int bx = blockIdx.x;
    if (bx < 512) {
        gemm128_body<1>(smem, qh, ql, mh, ml, nullptr, qmh, qml, nullptr, nullptr,
                        D_, D_, D_, D_, (bx >> 3) * 128, (bx & 7) * 128, 0, 1.f);
    } else {
        bx -= 512;
        gemm128_body<1>(smem, wvh, wvl, vh, vl, nullptr, vth, vtl, nullptr, nullptr,
                        D_, D_, D_, MS_, (bx >> 6) * 128, (bx & 63) * 128, 0, 1.f);
    }
}

// scores: e = exp(qM k^T / 32), split to eh/el, row partials
__global__ __launch_bounds__(256, 2)
void scores_kernel(const bf* qmh, const bf* qml, const bf* kh, const bf* kl,
                   bf* eh, bf* el, float* part)
{
    extern __shared__ char smem[];
    const size_t zq = (size_t)blockIdx.z * S_ * D_;
    const size_t zc = (size_t)blockIdx.z * S_ * S_;
    gemm128_body<2>(smem, qmh + zq, qml + zq, kh + zq, kl + zq,
                    nullptr, eh + zc, el + zc,
                    part + (size_t)blockIdx.z * S_ * 32, nullptr,
                    D_, D_, D_, S_,
                    blockIdx.y * 128, blockIdx.x * 128, blockIdx.x, 1.f / 32.f);
}

__global__ __launch_bounds__(256)
void reduce_inv_kernel(const float* __restrict__ part, float* __restrict__ invrs)
{
    const int row = blockIdx.x * 8 + (threadIdx.x >> 5);
    const int lane = threadIdx.x & 31;
    float vv = part[(size_t)row * 32 + lane];
#pragma unroll
    for (int off = 16; off > 0; off >>= 1)
        vv += __shfl_xor_sync(0xffffffffu, vv, off);
    if (lane == 0) invrs[row] = 1.f / vv;
}

// pv: out = diag(invrs) * e * vp
__global__ __launch_bounds__(256, 2)
void pv_kernel(const bf* eh, const bf* el, const bf* vth, const bf* vtl,
               float* out, const float* invrs)
{
    extern __shared__ char smem[];
    const size_t ze = (size_t)blockIdx.z * S_ * S_;
    const size_t zo = (size_t)blockIdx.z * S_ * D_;
    gemm128_body<3>(smem, eh + ze, el + ze, vth + (size_t)blockIdx.z * S_,
                    vtl + (size_t)blockIdx.z * S_,
                    out + zo, nullptr, nullptr, nullptr,
                    invrs + (size_t)blockIdx.z * S_,
                    S_, S_, MS_, D_,
                    blockIdx.y * 128, blockIdx.x * 128, 0, 1.f);
}

// ---------------------------------------------------------------------------
extern "C" void kernel_launch(void* const* d_in, const int* in_sizes, int n_in,
                              void* d_out, int out_size)
{
    const float* q  = (const float*)d_in[0];
    const float* k  = (const float*)d_in[1];
    const float* v  = (const float*)d_in[2];
    const float* wq = (const float*)d_in[3];
    const float* wk = (const float*)d_in[4];
    const float* wv = (const float*)d_in[5];
    float* out = (float*)d_out;

    bf *qh, *ql, *kh, *kl, *vh, *vl;
    bf *wqth, *wqtl, *wkth, *wktl, *wvh, *wvl;
    bf *mh, *ml, *qmh, *qml, *vth, *vtl, *eh, *el;
    float *part, *invrs;
    cudaGetSymbolAddress((void**)&qh, g_qh);     cudaGetSymbolAddress((void**)&ql, g_ql);
    cudaGetSymbolAddress((void**)&kh, g_kh);     cudaGetSymbolAddress((void**)&kl, g_kl);
    cudaGetSymbolAddress((void**)&vh, g_vh);     cudaGetSymbolAddress((void**)&vl, g_vl);
    cudaGetSymbolAddress((void**)&wqth, g_wqth); cudaGetSymbolAddress((void**)&wqtl, g_wqtl);
    cudaGetSymbolAddress((void**)&wkth, g_wkth); cudaGetSymbolAddress((void**)&wktl, g_wktl);
    cudaGetSymbolAddress((void**)&wvh, g_wvh);   cudaGetSymbolAddress((void**)&wvl, g_wvl);
    cudaGetSymbolAddress((void**)&mh, g_mh);     cudaGetSymbolAddress((void**)&ml, g_ml);
    cudaGetSymbolAddress((void**)&qmh, g_qmh);   cudaGetSymbolAddress((void**)&qml, g_qml);
    cudaGetSymbolAddress((void**)&vth, g_vth);   cudaGetSymbolAddress((void**)&vtl, g_vtl);
    cudaGetSymbolAddress((void**)&eh, g_eh);     cudaGetSymbolAddress((void**)&el, g_el);
    cudaGetSymbolAddress((void**)&part, g_part); cudaGetSymbolAddress((void**)&invrs, g_invrs);

    cudaFuncSetAttribute(prep2_kernel,    cudaFuncAttributeMaxDynamicSharedMemorySize, GSMEM64);
    cudaFuncSetAttribute(dualproj_kernel, cudaFuncAttributeMaxDynamicSharedMemorySize, GSMEM128);
    cudaFuncSetAttribute(scores_kernel,   cudaFuncAttributeMaxDynamicSharedMemorySize, GSMEM128);
    cudaFuncSetAttribute(pv_kernel,       cudaFuncAttributeMaxDynamicSharedMemorySize, GSMEM128);

    // 1) transpose+split wq, wk
    prep1_kernel<<<2048, 256>>>(wq, wqth, wqtl, wk, wkth, wktl);

    // 2) M' (64x64 GEMM, 256 blocks) overlapped with splits of q,k,v,wv
    prep2_kernel<<<256 + 3 * 1024 + 128, 256, GSMEM64>>>(
        wkth, wktl, wqth, wqtl, mh, ml,
        q, qh, ql, k, kh, kl, v, vh, vl, wv, wvh, wvl);

    // 3) qM = q M'^T  and  vp^T = Wv v^T  (one launch)
    dualproj_kernel<<<1024, 256, GSMEM128>>>(qh, ql, mh, ml, qmh, qml,
                                             wvh, wvl, vh, vl, vth, vtl);

    // 4) e = exp(qM k^T / 32) + row partial sums
    dim3 gs(16, 16, B_);
    scores_kernel<<<gs, 256, GSMEM128>>>(qmh, qml, kh, kl, eh, el, part);

    // 5) invrs = 1 / rowsum
    reduce_inv_kernel<<<MS_ / 8, 256>>>(part, invrs);

    // 6) out = diag(invrs) e vp
    dim3 go(8, 16, B_);
    pv_kernel<<<go, 256, GSMEM128>>>(eh, el, vth, vtl, out, invrs);
}

// round 7
// speedup vs baseline: 1.7527x; 1.4584x over previous
#include <cuda_runtime.h>
#include <cuda_fp16.h>
#include <math.h>
#include <cstdint>

// ---------------------------------------------------------------------------
// AttentionHead B=4, S=2048, D=1024 — mma.sync fp16 tiered precision.
// Projections: fp16 hi/lo split, 3-MMA (exact to ~2^-22).
// Scores: qM split x k single (2-MMA). PV: e single x vp single (1-MMA).
// Softmax fused: scores epilogue exp+round+partials; PV epilogue x invrs.
// ---------------------------------------------------------------------------

#define B_ 4
#define S_ 2048
#define D_ 1024
#define MS_ (B_ * S_)   // 8192
typedef __half hf;

// ---- scratch ----
__device__ __align__(16) hf g_qh [(size_t)MS_ * D_];
__device__ __align__(16) hf g_ql [(size_t)MS_ * D_];
__device__ __align__(16) hf g_ks [(size_t)MS_ * D_];   // k single
__device__ __align__(16) hf g_vh [(size_t)MS_ * D_];
__device__ __align__(16) hf g_vl [(size_t)MS_ * D_];
__device__ __align__(16) hf g_wqth[(size_t)D_ * D_];
__device__ __align__(16) hf g_wqtl[(size_t)D_ * D_];
__device__ __align__(16) hf g_wkth[(size_t)D_ * D_];
__device__ __align__(16) hf g_wktl[(size_t)D_ * D_];
__device__ __align__(16) hf g_wvh [(size_t)D_ * D_];
__device__ __align__(16) hf g_wvl [(size_t)D_ * D_];
__device__ __align__(16) hf g_mh  [(size_t)D_ * D_];
__device__ __align__(16) hf g_ml  [(size_t)D_ * D_];
__device__ __align__(16) hf g_qmh [(size_t)MS_ * D_];
__device__ __align__(16) hf g_qml [(size_t)MS_ * D_];
__device__ __align__(16) hf g_vts [(size_t)D_ * MS_];  // vp^T single [D, MS]
__device__ __align__(16) hf g_e   [(size_t)B_ * S_ * S_];  // exp(s) single
__device__ __align__(16) float g_part [(size_t)MS_ * 32];
__device__ __align__(16) float g_invrs[(size_t)MS_];

// ---- helpers ----
__device__ __forceinline__ uint32_t smem_u32(const void* p) {
    uint32_t a;
    asm("{ .reg .u64 t; cvta.to.shared.u64 t, %1; cvt.u32.u64 %0, t; }" : "=r"(a) : "l"(p));
    return a;
}
__device__ __forceinline__ void cp16s(uint32_t dst, const void* src) {
    asm volatile("cp.async.cg.shared.global [%0], [%1], 16;\n" :: "r"(dst), "l"(src));
}
__device__ __forceinline__ void cp_commit() { asm volatile("cp.async.commit_group;\n"); }
template <int N> __device__ __forceinline__ void cp_wait() {
    asm volatile("cp.async.wait_group %0;\n" :: "n"(N));
}
__device__ __forceinline__ void ldsm4(uint32_t (&r)[4], uint32_t addr) {
    asm volatile("ldmatrix.sync.aligned.m8n8.x4.shared.b16 {%0,%1,%2,%3}, [%4];"
                 : "=r"(r[0]), "=r"(r[1]), "=r"(r[2]), "=r"(r[3]) : "r"(addr));
}
__device__ __forceinline__ void mma_fp16(float (&d)[4], const uint32_t (&a)[4],
                                         uint32_t b0, uint32_t b1) {
    asm volatile(
        "mma.sync.aligned.m16n8k16.row.col.f32.f16.f16.f32 "
        "{%0,%1,%2,%3}, {%4,%5,%6,%7}, {%8,%9}, {%0,%1,%2,%3};\n"
        : "+f"(d[0]), "+f"(d[1]), "+f"(d[2]), "+f"(d[3])
        : "r"(a[0]), "r"(a[1]), "r"(a[2]), "r"(a[3]), "r"(b0), "r"(b1));
}
__device__ __forceinline__ void split2(float x, hf& h, hf& l) {
    h = __float2half_rn(x);
    l = __float2half_rn(x - __half2float(h));
}
__device__ __forceinline__ uint32_t packh(hf a, hf b) {
    __half2 p = __halves2half2(a, b);
    return *(uint32_t*)&p;
}

// ---------------------------------------------------------------------------
// smem tiles: 128 rows x 128B, SW128 XOR swizzle (chunk ^ (row&7)).
// split tile: BK=32, row = hi[0:32)|lo[0:32).  single tile: BK=64 natural.
// ---------------------------------------------------------------------------
constexpr int SUB16 = 128 * 128;           // 16 KB
constexpr int STAGE_PROJ = 2 * SUB16;      // A split + B split (BK=32) = 32 KB
constexpr int GSMEM_PROJ = 3 * STAGE_PROJ; // 96 KB
constexpr int STG_SC = 3 * SUB16;          // A0|A1 split + B single (BK=64) = 48 KB
constexpr int GSMEM_SC = 3 * STG_SC;       // 144 KB
constexpr int STG_PV = 2 * SUB16;          // A single + B single (BK=64) = 32 KB
constexpr int GSMEM_PV = 3 * STG_PV;       // 96 KB

__device__ __forceinline__ void fill_split(uint32_t dst, const hf* __restrict__ H,
                                           const hf* __restrict__ L,
                                           size_t ld, int rowbase, int k0, int tid) {
#pragma unroll
    for (int p = 0; p < 4; p++) {
        int idx = tid + p * 256;
        int r = idx >> 3, c = idx & 7;
        uint32_t off = (uint32_t)(r * 128) + ((((uint32_t)c) ^ ((uint32_t)r & 7)) << 4);
        const hf* src = (c < 4)
            ? H + (size_t)(rowbase + r) * ld + k0 + c * 8
            : L + (size_t)(rowbase + r) * ld + k0 + (c - 4) * 8;
        cp16s(dst + off, src);
    }
}
__device__ __forceinline__ void fill_single(uint32_t dst, const hf* __restrict__ X,
                                            size_t ld, int rowbase, int k0, int tid) {
#pragma unroll
    for (int p = 0; p < 4; p++) {
        int idx = tid + p * 256;
        int r = idx >> 3, c = idx & 7;
        uint32_t off = (uint32_t)(r * 128) + ((((uint32_t)c) ^ ((uint32_t)r & 7)) << 4);
        cp16s(dst + off, X + (size_t)(rowbase + r) * ld + k0 + c * 8);
    }
}

// ---------------------------------------------------------------------------
// both-split 3-MMA body (projections). EPI 1: split out; EPI 4: single out.
// ---------------------------------------------------------------------------
template <int EPI>
__device__ __forceinline__ void gemm128_split_body(
    char* smem,
    const hf* __restrict__ Ah, const hf* __restrict__ Al,
    const hf* __restrict__ Bh, const hf* __restrict__ Bl,
    hf* __restrict__ Ch, hf* __restrict__ Cl,
    int K, size_t lda, size_t ldb, size_t ldc, int bm, int bn)
{
    const uint32_t sbase = smem_u32(smem);
    const int tid = threadIdx.x;
    const int wid = tid >> 5, lane = tid & 31;
    const int wm = wid >> 1, wn = wid & 1;
    const int grp = lane >> 3, wi = lane & 7;
    const uint32_t xw = (uint32_t)wi << 4;
    const uint32_t aRow = (uint32_t)(wm * 32 + (grp & 1) * 8 + wi) * 128;
    const uint32_t bRow = (uint32_t)(wn * 64 + (grp >> 1) * 8 + wi) * 128;

    float acc[2][8][4];
#pragma unroll
    for (int i = 0; i < 2; i++)
#pragma unroll
        for (int j = 0; j < 8; j++)
#pragma unroll
            for (int r = 0; r < 4; r++) acc[i][j][r] = 0.f;

    auto fill_stage = [&](int s, int kt) {
        const uint32_t st = sbase + (uint32_t)s * STAGE_PROJ;
        fill_split(st,         Ah, Al, lda, bm, kt * 32, tid);
        fill_split(st + SUB16, Bh, Bl, ldb, bn, kt * 32, tid);
        cp_commit();
    };

    const int NT = K / 32;
    fill_stage(0, 0);
    fill_stage(1, 1);

    for (int kt = 0; kt < NT; kt++) {
        if (kt + 1 < NT) cp_wait<1>(); else cp_wait<0>();
        __syncthreads();
        if (kt + 2 < NT) fill_stage((kt + 2) % 3, kt + 2);

        const uint32_t st = sbase + (uint32_t)(kt % 3) * STAGE_PROJ;
#pragma unroll
        for (int kk = 0; kk < 2; kk++) {
            uint32_t ah[2][4], al[2][4];
            const uint32_t ak = ((uint32_t)(kk * 2 + (grp >> 1)) << 4) ^ xw;
#pragma unroll
            for (int mt = 0; mt < 2; mt++) {
                const uint32_t ao = st + aRow + (uint32_t)mt * 2048 + ak;
                ldsm4(ah[mt], ao);
                ldsm4(al[mt], ao ^ 64u);
            }
            const uint32_t bk = ((uint32_t)(kk * 2 + (grp & 1)) << 4) ^ xw;
#pragma unroll
            for (int np = 0; np < 4; np++) {
                uint32_t bh[4], bl[4];
                const uint32_t bo = st + SUB16 + bRow + (uint32_t)np * 2048 + bk;
                ldsm4(bh, bo);
                ldsm4(bl, bo ^ 64u);
#pragma unroll
                for (int mt = 0; mt < 2; mt++)
#pragma unroll
                    for (int half = 0; half < 2; half++) {
                        const int nt = np * 2 + half;
                        const int h = half * 2;
                        mma_fp16(acc[mt][nt], ah[mt], bh[h], bh[h + 1]);
                        mma_fp16(acc[mt][nt], ah[mt], bl[h], bl[h + 1]);
                        mma_fp16(acc[mt][nt], al[mt], bh[h], bh[h + 1]);
                    }
            }
        }
    }

    const int g = lane >> 2, t = lane & 3;
#pragma unroll
    for (int mt = 0; mt < 2; mt++)
#pragma unroll
        for (int nt = 0; nt < 8; nt++) {
            const size_t row0 = (size_t)(bm + wm * 32 + mt * 16 + g);
            const size_t col  = (size_t)(bn + wn * 64 + nt * 8 + 2 * t);
            if (EPI == 1) {
                hf h0, l0, h1, l1;
                split2(acc[mt][nt][0], h0, l0); split2(acc[mt][nt][1], h1, l1);
                *(uint32_t*)(Ch + row0 * ldc + col) = packh(h0, h1);
                *(uint32_t*)(Cl + row0 * ldc + col) = packh(l0, l1);
                split2(acc[mt][nt][2], h0, l0); split2(acc[mt][nt][3], h1, l1);
                *(uint32_t*)(Ch + (row0 + 8) * ldc + col) = packh(h0, h1);
                *(uint32_t*)(Cl + (row0 + 8) * ldc + col) = packh(l0, l1);
            } else { // EPI == 4: single fp16 out
                *(uint32_t*)(Ch + row0 * ldc + col) =
                    packh(__float2half_rn(acc[mt][nt][0]), __float2half_rn(acc[mt][nt][1]));
                *(uint32_t*)(Ch + (row0 + 8) * ldc + col) =
                    packh(__float2half_rn(acc[mt][nt][2]), __float2half_rn(acc[mt][nt][3]));
            }
        }
}

// ---------------------------------------------------------------------------
// 64x64 both-split 3-MMA (M'), split out.
// ---------------------------------------------------------------------------
constexpr int SUB64 = 64 * 128;
constexpr int STAGE64 = 2 * SUB64;
constexpr int GSMEM64 = 3 * STAGE64;   // 48 KB

__device__ __forceinline__ void fill64(uint32_t dst, const hf* __restrict__ H,
                                       const hf* __restrict__ L,
                                       size_t ld, int rowbase, int k0, int tid) {
#pragma unroll
    for (int p = 0; p < 2; p++) {
        int idx = tid + p * 256;
        int r = idx >> 3, c = idx & 7;
        uint32_t off = (uint32_t)(r * 128) + ((((uint32_t)c) ^ ((uint32_t)r & 7)) << 4);
        const hf* src = (c < 4)
            ? H + (size_t)(rowbase + r) * ld + k0 + c * 8
            : L + (size_t)(rowbase + r) * ld + k0 + (c - 4) * 8;
        cp16s(dst + off, src);
    }
}

__device__ __forceinline__ void gemm64_body(
    char* smem,
    const hf* __restrict__ Ah, const hf* __restrict__ Al,
    const hf* __restrict__ Bh, const hf* __restrict__ Bl,
    hf* __restrict__ Ch, hf* __restrict__ Cl,
    int K, size_t ld, int bm, int bn)
{
    const uint32_t sbase = smem_u32(smem);
    const int tid = threadIdx.x;
    const int wid = tid >> 5, lane = tid & 31;
    const int wm = wid >> 1, wn = wid & 1;
    const int grp = lane >> 3, wi = lane & 7;
    const uint32_t xw = (uint32_t)wi << 4;
    const uint32_t aRow = (uint32_t)(wm * 16 + (grp & 1) * 8 + wi) * 128;
    const uint32_t bRow = (uint32_t)(wn * 32 + (grp >> 1) * 8 + wi) * 128;

    float acc[4][4];
#pragma unroll
    for (int j = 0; j < 4; j++)
#pragma unroll
        for (int r = 0; r < 4; r++) acc[j][r] = 0.f;

    auto fill_stage = [&](int s, int kt) {
        const uint32_t st = sbase + (uint32_t)s * STAGE64;
        fill64(st,         Ah, Al, ld, bm, kt * 32, tid);
        fill64(st + SUB64, Bh, Bl, ld, bn, kt * 32, tid);
        cp_commit();
    };

    const int NT = K / 32;
    fill_stage(0, 0);
    fill_stage(1, 1);

    for (int kt = 0; kt < NT; kt++) {
        if (kt + 1 < NT) cp_wait<1>(); else cp_wait<0>();
        __syncthreads();
        if (kt + 2 < NT) fill_stage((kt + 2) % 3, kt + 2);

        const uint32_t st = sbase + (uint32_t)(kt % 3) * STAGE64;
#pragma unroll
        for (int kk = 0; kk < 2; kk++) {
            uint32_t ah[4], al[4];
            const uint32_t ak = ((uint32_t)(kk * 2 + (grp >> 1)) << 4) ^ xw;
            const uint32_t ao = st + aRow + ak;
            ldsm4(ah, ao);
            ldsm4(al, ao ^ 64u);
            const uint32_t bk = ((uint32_t)(kk * 2 + (grp & 1)) << 4) ^ xw;
#pragma unroll
            for (int np = 0; np < 2; np++) {
                uint32_t bh[4], bl[4];
                const uint32_t bo = st + SUB64 + bRow + (uint32_t)np * 2048 + bk;
                ldsm4(bh, bo);
                ldsm4(bl, bo ^ 64u);
#pragma unroll
                for (int half = 0; half < 2; half++) {
                    const int nt = np * 2 + half;
                    const int h = half * 2;
                    mma_fp16(acc[nt], ah, bh[h], bh[h + 1]);
                    mma_fp16(acc[nt], ah, bl[h], bl[h + 1]);
                    mma_fp16(acc[nt], al, bh[h], bh[h + 1]);
                }
            }
        }
    }

    const int g = lane >> 2, t = lane & 3;
#pragma unroll
    for (int nt = 0; nt < 4; nt++) {
        const size_t row0 = (size_t)(bm + wm * 16 + g);
        const size_t col  = (size_t)(bn + wn * 32 + nt * 8 + 2 * t);
        hf h0, l0, h1, l1;
        split2(acc[nt][0], h0, l0); split2(acc[nt][1], h1, l1);
        *(uint32_t*)(Ch + row0 * ld + col) = packh(h0, h1);
        *(uint32_t*)(Cl + row0 * ld + col) = packh(l0, l1);
        split2(acc[nt][2], h0, l0); split2(acc[nt][3], h1, l1);
        *(uint32_t*)(Ch + (row0 + 8) * ld + col) = packh(h0, h1);
        *(uint32_t*)(Cl + (row0 + 8) * ld + col) = packh(l0, l1);
    }
}

// ---------------------------------------------------------------------------
// prep1: transpose+split wq, wk (fp16)
// ---------------------------------------------------------------------------
__global__ __launch_bounds__(256)
void prep1_kernel(const float* __restrict__ wq, hf* __restrict__ wqth, hf* __restrict__ wqtl,
                  const float* __restrict__ wk, hf* __restrict__ wkth, hf* __restrict__ wktl)
{
    __shared__ float tile[32][33];
    const int tb = blockIdx.x & 1023;
    const float* x = (blockIdx.x < 1024) ? wq : wk;
    hf* h = (blockIdx.x < 1024) ? wqth : wkth;
    hf* l = (blockIdx.x < 1024) ? wqtl : wktl;
    const int tx = threadIdx.x & 31, ty = threadIdx.x >> 5;
    const int r0 = (tb >> 5) * 32, c0 = (tb & 31) * 32;
#pragma unroll
    for (int i = 0; i < 4; i++)
        tile[ty + i * 8][tx] = x[(size_t)(r0 + ty + i * 8) * D_ + c0 + tx];
    __syncthreads();
#pragma unroll
    for (int i = 0; i < 4; i++) {
        float vv = tile[tx][ty + i * 8];
        hf hh, ll;
        split2(vv, hh, ll);
        h[(size_t)(c0 + ty + i * 8) * D_ + r0 + tx] = hh;
        l[(size_t)(c0 + ty + i * 8) * D_ + r0 + tx] = ll;
    }
}

// ---------------------------------------------------------------------------
// prep2: [0,256) M' 64x64; then splits of q, v, wv; k single convert.
// ---------------------------------------------------------------------------
__device__ __forceinline__ void split_block(const float* __restrict__ x,
                                            hf* __restrict__ h, hf* __restrict__ l,
                                            size_t bi) {
    const float4* x4 = (const float4*)x;
    uint2* h2 = (uint2*)h;
    uint2* l2 = (uint2*)l;
    const size_t base = bi * 2048 + threadIdx.x;
#pragma unroll
    for (int j = 0; j < 8; j++) {
        float4 vv = x4[base + j * 256];
        hf h0, l0, h1, l1, h2b, l2b, h3, l3;
        split2(vv.x, h0, l0); split2(vv.y, h1, l1);
        split2(vv.z, h2b, l2b); split2(vv.w, h3, l3);
        h2[base + j * 256] = make_uint2(packh(h0, h1), packh(h2b, h3));
        l2[base + j * 256] = make_uint2(packh(l0, l1), packh(l2b, l3));
    }
}
__device__ __forceinline__ void single_conv_block(const float* __restrict__ x,
                                                  hf* __restrict__ h, size_t bi) {
    const float4* x4 = (const float4*)x;
    uint2* h2 = (uint2*)h;
    const size_t base = bi * 2048 + threadIdx.x;
#pragma unroll
    for (int j = 0; j < 8; j++) {
        float4 vv = x4[base + j * 256];
        h2[base + j * 256] = make_uint2(
            packh(__float2half_rn(vv.x), __float2half_rn(vv.y)),
            packh(__float2half_rn(vv.z), __float2half_rn(vv.w)));
    }
}

__global__ __launch_bounds__(256, 2)
void prep2_kernel(const hf* __restrict__ wkth, const hf* __restrict__ wktl,
                  const hf* __restrict__ wqth, const hf* __restrict__ wqtl,
                  hf* __restrict__ mh, hf* __restrict__ ml,
                  const float* __restrict__ q, hf* __restrict__ qh, hf* __restrict__ ql,
                  const float* __restrict__ k, hf* __restrict__ ks,
                  const float* __restrict__ v, hf* __restrict__ vh, hf* __restrict__ vl,
                  const float* __restrict__ wv, hf* __restrict__ wvh, hf* __restrict__ wvl)
{
    extern __shared__ char smem[];
    const int bx = blockIdx.x;
    if (bx < 256) {
        gemm64_body(smem, wkth, wktl, wqth, wqtl, mh, ml,
                    D_, D_, (bx >> 4) * 64, (bx & 15) * 64);
    } else {
        int b = bx - 256;
        if (b < 1024)       split_block(q, qh, ql, (size_t)b);
        else if (b < 2048)  single_conv_block(k, ks, (size_t)(b - 1024));
        else if (b < 3072)  split_block(v, vh, vl, (size_t)(b - 2048));
        else                split_block(wv, wvh, wvl, (size_t)(b - 3072));
    }
}

// ---------------------------------------------------------------------------
// dualproj: qM split-out (512 blocks) + vp^T single-out (512 blocks)
// ---------------------------------------------------------------------------
__global__ __launch_bounds__(256, 2)
void dualproj_kernel(const hf* qh, const hf* ql, const hf* mh, const hf* ml,
                     hf* qmh, hf* qml,
                     const hf* wvh, const hf* wvl, const hf* vh, const hf* vl,
                     hf* vts)
{
    extern __shared__ char smem[];
    int bx = blockIdx.x;
    if (bx < 512) {
        gemm128_split_body<1>(smem, qh, ql, mh, ml, qmh, qml,
                              D_, D_, D_, D_, (bx >> 3) * 128, (bx & 7) * 128);
    } else {
        bx -= 512;
        gemm128_split_body<4>(smem, wvh, wvl, vh, vl, vts, nullptr,
                              D_, D_, D_, MS_, (bx >> 6) * 128, (bx & 63) * 128);
    }
}

// ---------------------------------------------------------------------------
// scores: A = qM split, B = k single. 2-MMA. BK=64, 3 stages (144KB, 1 CTA).
// Epilogue: e = rn(exp(acc/32)) single fp16 + deterministic row partials.
// ---------------------------------------------------------------------------
__global__ __launch_bounds__(256, 1)
void scores_kernel(const hf* __restrict__ qmh, const hf* __restrict__ qml,
                   const hf* __restrict__ ks, hf* __restrict__ e,
                   float* __restrict__ part)
{
    extern __shared__ char smem[];
    const uint32_t sbase = smem_u32(smem);
    const int tid = threadIdx.x;
    const int wid = tid >> 5, lane = tid & 31;
    const int wm = wid >> 1, wn = wid & 1;
    const int grp = lane >> 3, wi = lane & 7;
    const uint32_t xw = (uint32_t)wi << 4;
    const uint32_t aRow = (uint32_t)(wm * 32 + (grp & 1) * 8 + wi) * 128;
    const uint32_t bRow = (uint32_t)(wn * 64 + (grp >> 1) * 8 + wi) * 128;

    const size_t zq = (size_t)blockIdx.z * S_ * D_;
    const hf* Ah = qmh + zq;
    const hf* Al = qml + zq;
    const hf* Bs = ks + zq;
    hf* E = e + (size_t)blockIdx.z * S_ * S_;
    float* pp = part + (size_t)blockIdx.z * S_ * 32;
    const int bm = blockIdx.y * 128, bn = blockIdx.x * 128;

    float acc[2][8][4];
#pragma unroll
    for (int i = 0; i < 2; i++)
#pragma unroll
        for (int j = 0; j < 8; j++)
#pragma unroll
            for (int r = 0; r < 4; r++) acc[i][j][r] = 0.f;

    auto fill_stage = [&](int s, int kt) {
        const uint32_t st = sbase + (uint32_t)s * STG_SC;
        const int k0 = kt * 64;
        fill_split(st,             Ah, Al, D_, bm, k0, tid);
        fill_split(st + SUB16,     Ah, Al, D_, bm, k0 + 32, tid);
        fill_single(st + 2 * SUB16, Bs, D_, bn, k0, tid);
        cp_commit();
    };

    const int NT = D_ / 64;   // 16
    fill_stage(0, 0);
    fill_stage(1, 1);

    for (int kt = 0; kt < NT; kt++) {
        if (kt + 1 < NT) cp_wait<1>(); else cp_wait<0>();
        __syncthreads();
        if (kt + 2 < NT) fill_stage((kt + 2) % 3, kt + 2);

        const uint32_t st = sbase + (uint32_t)(kt % 3) * STG_SC;
#pragma unroll
        for (int kk = 0; kk < 4; kk++) {              // k16 steps in BK=64
            uint32_t ah[2][4], al[2][4];
            const uint32_t aBase = st + (uint32_t)(kk >> 1) * SUB16;
            const uint32_t ak = ((uint32_t)((kk & 1) * 2 + (grp >> 1)) << 4) ^ xw;
#pragma unroll
            for (int mt = 0; mt < 2; mt++) {
                const uint32_t ao = aBase + aRow + (uint32_t)mt * 2048 + ak;
                ldsm4(ah[mt], ao);
                ldsm4(al[mt], ao ^ 64u);
            }
            const uint32_t bk = ((uint32_t)(kk * 2 + (grp & 1)) << 4) ^ xw;
#pragma unroll
            for (int np = 0; np < 4; np++) {
                uint32_t bb[4];
                ldsm4(bb, st + 2 * SUB16 + bRow + (uint32_t)np * 2048 + bk);
#pragma unroll
                for (int mt = 0; mt < 2; mt++)
#pragma unroll
                    for (int half = 0; half < 2; half++) {
                        const int nt = np * 2 + half;
                        const int h = half * 2;
                        mma_fp16(acc[mt][nt], ah[mt], bb[h], bb[h + 1]);
                        mma_fp16(acc[mt][nt], al[mt], bb[h], bb[h + 1]);
                    }
            }
        }
    }

    const int g = lane >> 2, t = lane & 3;
#pragma unroll
    for (int mt = 0; mt < 2; mt++) {
        float p0 = 0.f, p1 = 0.f;
#pragma unroll
        for (int nt = 0; nt < 8; nt++) {
            const size_t row0 = (size_t)(bm + wm * 32 + mt * 16 + g);
            const size_t col  = (size_t)(bn + wn * 64 + nt * 8 + 2 * t);
            hf e0 = __float2half_rn(__expf(acc[mt][nt][0] * (1.f / 32.f)));
            hf e1 = __float2half_rn(__expf(acc[mt][nt][1] * (1.f / 32.f)));
            hf e2 = __float2half_rn(__expf(acc[mt][nt][2] * (1.f / 32.f)));
            hf e3 = __float2half_rn(__expf(acc[mt][nt][3] * (1.f / 32.f)));
            p0 += __half2float(e0) + __half2float(e1);
            p1 += __half2float(e2) + __half2float(e3);
            *(uint32_t*)(E + row0 * S_ + col)       = packh(e0, e1);
            *(uint32_t*)(E + (row0 + 8) * S_ + col) = packh(e2, e3);
        }
        p0 += __shfl_xor_sync(0xffffffffu, p0, 1);
        p0 += __shfl_xor_sync(0xffffffffu, p0, 2);
        p1 += __shfl_xor_sync(0xffffffffu, p1, 1);
        p1 += __shfl_xor_sync(0xffffffffu, p1, 2);
        if (t == 0) {
            const int row0 = bm + wm * 32 + mt * 16 + g;
            pp[(size_t)row0 * 32 + blockIdx.x * 2 + wn]       = p0;
            pp[(size_t)(row0 + 8) * 32 + blockIdx.x * 2 + wn] = p1;
        }
    }
}

__global__ __launch_bounds__(256)
void reduce_inv_kernel(const float* __restrict__ part, float* __restrict__ invrs)
{
    const int row = blockIdx.x * 8 + (threadIdx.x >> 5);
    const int lane = threadIdx.x & 31;
    float vv = part[(size_t)row * 32 + lane];
#pragma unroll
    for (int off = 16; off > 0; off >>= 1)
        vv += __shfl_xor_sync(0xffffffffu, vv, off);
    if (lane == 0) invrs[row] = 1.f / vv;
}

// ---------------------------------------------------------------------------
// pv: A = e single, B = vp^T single. 1-MMA. BK=64, 3 stages (96KB, 2 CTAs).
// ---------------------------------------------------------------------------
__global__ __launch_bounds__(256, 2)
void pv_kernel(const hf* __restrict__ e, const hf* __restrict__ vts,
               float* __restrict__ out, const float* __restrict__ invrs)
{
    extern __shared__ char smem[];
    const uint32_t sbase = smem_u32(smem);
    const int tid = threadIdx.x;
    const int wid = tid >> 5, lane = tid & 31;
    const int wm = wid >> 1, wn = wid & 1;
    const int grp = lane >> 3, wi = lane & 7;
    const uint32_t xw = (uint32_t)wi << 4;
    const uint32_t aRow = (uint32_t)(wm * 32 + (grp & 1) * 8 + wi) * 128;
    const uint32_t bRow = (uint32_t)(wn * 64 + (grp >> 1) * 8 + wi) * 128;

    const hf* A = e + (size_t)blockIdx.z * S_ * S_;
    const hf* Bv = vts + (size_t)blockIdx.z * S_;
    float* C = out + (size_t)blockIdx.z * S_ * D_;
    const float* inv = invrs + (size_t)blockIdx.z * S_;
    const int bm = blockIdx.y * 128, bn = blockIdx.x * 128;

    float acc[2][8][4];
#pragma unroll
    for (int i = 0; i < 2; i++)
#pragma unroll
        for (int j = 0; j < 8; j++)
#pragma unroll
            for (int r = 0; r < 4; r++) acc[i][j][r] = 0.f;

    auto fill_stage = [&](int s, int kt) {
        const uint32_t st = sbase + (uint32_t)s * STG_PV;
        const int k0 = kt * 64;
        fill_single(st,         A,  S_,  bm, k0, tid);
        fill_single(st + SUB16, Bv, MS_, bn, k0, tid);
        cp_commit();
    };

    const int NT = S_ / 64;   // 32
    fill_stage(0, 0);
    fill_stage(1, 1);

    for (int kt = 0; kt < NT; kt++) {
        if (kt + 1 < NT) cp_wait<1>(); else cp_wait<0>();
        __syncthreads();
        if (kt + 2 < NT) fill_stage((kt + 2) % 3, kt + 2);

        const uint32_t st = sbase + (uint32_t)(kt % 3) * STG_PV;
#pragma unroll
        for (int kk = 0; kk < 4; kk++) {
            uint32_t aa[2][4];
            const uint32_t ak = ((uint32_t)(kk * 2 + (grp >> 1)) << 4) ^ xw;
#pragma unroll
            for (int mt = 0; mt < 2; mt++)
                ldsm4(aa[mt], st + aRow + (uint32_t)mt * 2048 + ak);
            const uint32_t bk = ((uint32_t)(kk * 2 + (grp & 1)) << 4) ^ xw;
#pragma unroll
            for (int np = 0; np < 4; np++) {
                uint32_t bb[4];
                ldsm4(bb, st + SUB16 + bRow + (uint32_t)np * 2048 + bk);
#pragma unroll
                for (int mt = 0; mt < 2; mt++)
#pragma unroll
                    for (int half = 0; half < 2; half++)
                        mma_fp16(acc[mt][np * 2 + half], aa[mt],
                                 bb[half * 2], bb[half * 2 + 1]);
            }
        }
    }

    const int g = lane >> 2, t = lane & 3;
#pragma unroll
    for (int mt = 0; mt < 2; mt++)
#pragma unroll
        for (int nt = 0; nt < 8; nt++) {
            const size_t row0 = (size_t)(bm + wm * 32 + mt * 16 + g);
            const size_t col  = (size_t)(bn + wn * 64 + nt * 8 + 2 * t);
            const float i0 = inv[row0], i1 = inv[row0 + 8];
            *(float2*)(C + row0 * D_ + col) =
                make_float2(acc[mt][nt][0] * i0, acc[mt][nt][1] * i0);
            *(float2*)(C + (row0 + 8) * D_ + col) =
                make_float2(acc[mt][nt][2] * i1, acc[mt][nt][3] * i1);
        }
}

// ---------------------------------------------------------------------------
extern "C" void kernel_launch(void* const* d_in, const int* in_sizes, int n_in,
                              void* d_out, int out_size)
{
    const float* q  = (const float*)d_in[0];
    const float* k  = (const float*)d_in[1];
    const float* v  = (const float*)d_in[2];
    const float* wq = (const float*)d_in[3];
    const float* wk = (const float*)d_in[4];
    const float* wv = (const float*)d_in[5];
    float* out = (float*)d_out;

    hf *qh, *ql, *ks, *vh, *vl;
    hf *wqth, *wqtl, *wkth, *wktl, *wvh, *wvl;
    hf *mh, *ml, *qmh, *qml, *vts, *e;
    float *part, *invrs;
    cudaGetSymbolAddress((void**)&qh, g_qh);     cudaGetSymbolAddress((void**)&ql, g_ql);
    cudaGetSymbolAddress((void**)&ks, g_ks);
    cudaGetSymbolAddress((void**)&vh, g_vh);     cudaGetSymbolAddress((void**)&vl, g_vl);
    cudaGetSymbolAddress((void**)&wqth, g_wqth); cudaGetSymbolAddress((void**)&wqtl, g_wqtl);
    cudaGetSymbolAddress((void**)&wkth, g_wkth); cudaGetSymbolAddress((void**)&wktl, g_wktl);
    cudaGetSymbolAddress((void**)&wvh, g_wvh);   cudaGetSymbolAddress((void**)&wvl, g_wvl);
    cudaGetSymbolAddress((void**)&mh, g_mh);     cudaGetSymbolAddress((void**)&ml, g_ml);
    cudaGetSymbolAddress((void**)&qmh, g_qmh);   cudaGetSymbolAddress((void**)&qml, g_qml);
    cudaGetSymbolAddress((void**)&vts, g_vts);   cudaGetSymbolAddress((void**)&e, g_e);
    cudaGetSymbolAddress((void**)&part, g_part); cudaGetSymbolAddress((void**)&invrs, g_invrs);

    cudaFuncSetAttribute(prep2_kernel,    cudaFuncAttributeMaxDynamicSharedMemorySize, GSMEM64);
    cudaFuncSetAttribute(dualproj_kernel, cudaFuncAttributeMaxDynamicSharedMemorySize, GSMEM_PROJ);
    cudaFuncSetAttribute(scores_kernel,   cudaFuncAttributeMaxDynamicSharedMemorySize, GSMEM_SC);
    cudaFuncSetAttribute(pv_kernel,       cudaFuncAttributeMaxDynamicSharedMemorySize, GSMEM_PV);

    // 1) transpose+split wq, wk
    prep1_kernel<<<2048, 256>>>(wq, wqth, wqtl, wk, wkth, wktl);

    // 2) M' (256 blocks) overlapped with q/v/wv splits + k single convert
    prep2_kernel<<<256 + 3 * 1024 + 128, 256, GSMEM64>>>(
        wkth, wktl, wqth, wqtl, mh, ml,
        q, qh, ql, k, ks, v, vh, vl, wv, wvh, wvl);

    // 3) qM = q M'^T (split out) and vp^T = Wv v^T (single out)
    dualproj_kernel<<<1024, 256, GSMEM_PROJ>>>(qh, ql, mh, ml, qmh, qml,
                                               wvh, wvl, vh, vl, vts);

    // 4) e = exp(qM k^T / 32) (single fp16) + row partials
    dim3 gs(16, 16, B_);
    scores_kernel<<<gs, 256, GSMEM_SC>>>(qmh, qml, ks, e, part);

    // 5) invrs = 1 / rowsum
    reduce_inv_kernel<<<MS_ / 8, 256>>>(part, invrs);

    // 6) out = diag(invrs) e vp
    dim3 go(8, 16, B_);
    pv_kernel<<<go, 256, GSMEM_PV>>>(e, vts, out, invrs);
}

// round 8
// speedup vs baseline: 2.5255x; 1.4409x over previous
#include <cuda_runtime.h>
#include <cuda_fp16.h>
#include <math.h>
#include <cstdint>

// ---------------------------------------------------------------------------
// AttentionHead B=4, S=2048, D=1024 — mma.sync fp16 tiered precision v2.
// M' = Wk^T Wq (3-MMA from weight splits, rounded to fp16 single).
// qM = q_single x M'_single (1-MMA). scores = qM x k (1-MMA).
// vp^T = Wv x v (3-MMA from splits, single out). PV = e x vp (1-MMA).
// Softmax fused into scores epilogue (exp+partials) and PV epilogue (x invrs).
// ---------------------------------------------------------------------------

#define B_ 4
#define S_ 2048
#define D_ 1024
#define MS_ (B_ * S_)   // 8192
typedef __half hf;

// ---- scratch ----
__device__ __align__(16) hf g_qs [(size_t)MS_ * D_];   // q single
__device__ __align__(16) hf g_ks [(size_t)MS_ * D_];   // k single
__device__ __align__(16) hf g_vh [(size_t)MS_ * D_];
__device__ __align__(16) hf g_vl [(size_t)MS_ * D_];
__device__ __align__(16) hf g_wqth[(size_t)D_ * D_];
__device__ __align__(16) hf g_wqtl[(size_t)D_ * D_];
__device__ __align__(16) hf g_wkth[(size_t)D_ * D_];
__device__ __align__(16) hf g_wktl[(size_t)D_ * D_];
__device__ __align__(16) hf g_wvh [(size_t)D_ * D_];
__device__ __align__(16) hf g_wvl [(size_t)D_ * D_];
__device__ __align__(16) hf g_ms  [(size_t)D_ * D_];   // M' single
__device__ __align__(16) hf g_qms [(size_t)MS_ * D_];  // qM single
__device__ __align__(16) hf g_vts [(size_t)D_ * MS_];  // vp^T single [D, MS]
__device__ __align__(16) hf g_e   [(size_t)B_ * S_ * S_];
__device__ __align__(16) float g_part [(size_t)MS_ * 32];
__device__ __align__(16) float g_invrs[(size_t)MS_];

// ---- helpers ----
__device__ __forceinline__ uint32_t smem_u32(const void* p) {
    uint32_t a;
    asm("{ .reg .u64 t; cvta.to.shared.u64 t, %1; cvt.u32.u64 %0, t; }" : "=r"(a) : "l"(p));
    return a;
}
__device__ __forceinline__ void cp16s(uint32_t dst, const void* src) {
    asm volatile("cp.async.cg.shared.global [%0], [%1], 16;\n" :: "r"(dst), "l"(src));
}
__device__ __forceinline__ void cp_commit() { asm volatile("cp.async.commit_group;\n"); }
template <int N> __device__ __forceinline__ void cp_wait() {
    asm volatile("cp.async.wait_group %0;\n" :: "n"(N));
}
__device__ __forceinline__ void ldsm4(uint32_t (&r)[4], uint32_t addr) {
    asm volatile("ldmatrix.sync.aligned.m8n8.x4.shared.b16 {%0,%1,%2,%3}, [%4];"
                 : "=r"(r[0]), "=r"(r[1]), "=r"(r[2]), "=r"(r[3]) : "r"(addr));
}
__device__ __forceinline__ void mma_fp16(float (&d)[4], const uint32_t (&a)[4],
                                         uint32_t b0, uint32_t b1) {
    asm volatile(
        "mma.sync.aligned.m16n8k16.row.col.f32.f16.f16.f32 "
        "{%0,%1,%2,%3}, {%4,%5,%6,%7}, {%8,%9}, {%0,%1,%2,%3};\n"
        : "+f"(d[0]), "+f"(d[1]), "+f"(d[2]), "+f"(d[3])
        : "r"(a[0]), "r"(a[1]), "r"(a[2]), "r"(a[3]), "r"(b0), "r"(b1));
}
__device__ __forceinline__ void split2(float x, hf& h, hf& l) {
    h = __float2half_rn(x);
    l = __float2half_rn(x - __half2float(h));
}
__device__ __forceinline__ uint32_t packh(hf a, hf b) {
    __half2 p = __halves2half2(a, b);
    return *(uint32_t*)&p;
}

// ---------------------------------------------------------------------------
// smem tiles: 128 rows x 128B, SW128 XOR swizzle (chunk ^ (row&7)).
// split tile: BK=32, row = hi[0:32)|lo[0:32).  single tile: BK=64 natural.
// ---------------------------------------------------------------------------
constexpr int SUB16 = 128 * 128;           // 16 KB
constexpr int STAGE_PROJ = 2 * SUB16;      // A split + B split (BK=32) = 32 KB
constexpr int GSMEM_PROJ = 3 * STAGE_PROJ; // 96 KB
constexpr int STG_SS = 2 * SUB16;          // A single + B single (BK=64) = 32 KB
constexpr int GSMEM_SS = 3 * STG_SS;       // 96 KB

__device__ __forceinline__ void fill_split(uint32_t dst, const hf* __restrict__ H,
                                           const hf* __restrict__ L,
                                           size_t ld, int rowbase, int k0, int tid) {
#pragma unroll
    for (int p = 0; p < 4; p++) {
        int idx = tid + p * 256;
        int r = idx >> 3, c = idx & 7;
        uint32_t off = (uint32_t)(r * 128) + ((((uint32_t)c) ^ ((uint32_t)r & 7)) << 4);
        const hf* src = (c < 4)
            ? H + (size_t)(rowbase + r) * ld + k0 + c * 8
            : L + (size_t)(rowbase + r) * ld + k0 + (c - 4) * 8;
        cp16s(dst + off, src);
    }
}
__device__ __forceinline__ void fill_single(uint32_t dst, const hf* __restrict__ X,
                                            size_t ld, int rowbase, int k0, int tid) {
#pragma unroll
    for (int p = 0; p < 4; p++) {
        int idx = tid + p * 256;
        int r = idx >> 3, c = idx & 7;
        uint32_t off = (uint32_t)(r * 128) + ((((uint32_t)c) ^ ((uint32_t)r & 7)) << 4);
        cp16s(dst + off, X + (size_t)(rowbase + r) * ld + k0 + c * 8);
    }
}

// ---------------------------------------------------------------------------
// single x single 1-MMA body, BK=64.
// EPI 2: e=rn(exp(acc*1/32)) -> Ch + deterministic row partials.
// EPI 3: fp32 Cf scaled by invrs[row].  EPI 4: single fp16 Ch.
// ---------------------------------------------------------------------------
template <int EPI>
__device__ __forceinline__ void gemm128_ss_body(
    char* smem, const hf* __restrict__ A, const hf* __restrict__ Bx,
    size_t lda, size_t ldb, int K,
    hf* __restrict__ Ch, float* __restrict__ Cf, size_t ldc,
    float* __restrict__ part, const float* __restrict__ invrs,
    int bm, int bn, int bx)
{
    const uint32_t sbase = smem_u32(smem);
    const int tid = threadIdx.x;
    const int wid = tid >> 5, lane = tid & 31;
    const int wm = wid >> 1, wn = wid & 1;
    const int grp = lane >> 3, wi = lane & 7;
    const uint32_t xw = (uint32_t)wi << 4;
    const uint32_t aRow = (uint32_t)(wm * 32 + (grp & 1) * 8 + wi) * 128;
    const uint32_t bRow = (uint32_t)(wn * 64 + (grp >> 1) * 8 + wi) * 128;

    float acc[2][8][4];
#pragma unroll
    for (int i = 0; i < 2; i++)
#pragma unroll
        for (int j = 0; j < 8; j++)
#pragma unroll
            for (int r = 0; r < 4; r++) acc[i][j][r] = 0.f;

    auto fill_stage = [&](int s, int kt) {
        const uint32_t st = sbase + (uint32_t)s * STG_SS;
        const int k0 = kt * 64;
        fill_single(st,         A,  lda, bm, k0, tid);
        fill_single(st + SUB16, Bx, ldb, bn, k0, tid);
        cp_commit();
    };

    const int NT = K / 64;
    fill_stage(0, 0);
    fill_stage(1, 1);

    for (int kt = 0; kt < NT; kt++) {
        if (kt + 1 < NT) cp_wait<1>(); else cp_wait<0>();
        __syncthreads();
        if (kt + 2 < NT) fill_stage((kt + 2) % 3, kt + 2);

        const uint32_t st = sbase + (uint32_t)(kt % 3) * STG_SS;
#pragma unroll
        for (int kk = 0; kk < 4; kk++) {
            uint32_t aa[2][4];
            const uint32_t ak = ((uint32_t)(kk * 2 + (grp >> 1)) << 4) ^ xw;
#pragma unroll
            for (int mt = 0; mt < 2; mt++)
                ldsm4(aa[mt], st + aRow + (uint32_t)mt * 2048 + ak);
            const uint32_t bk = ((uint32_t)(kk * 2 + (grp & 1)) << 4) ^ xw;
#pragma unroll
            for (int np = 0; np < 4; np++) {
                uint32_t bb[4];
                ldsm4(bb, st + SUB16 + bRow + (uint32_t)np * 2048 + bk);
#pragma unroll
                for (int mt = 0; mt < 2; mt++)
#pragma unroll
                    for (int half = 0; half < 2; half++)
                        mma_fp16(acc[mt][np * 2 + half], aa[mt],
                                 bb[half * 2], bb[half * 2 + 1]);
            }
        }
    }

    const int g = lane >> 2, t = lane & 3;
#pragma unroll
    for (int mt = 0; mt < 2; mt++) {
        float p0 = 0.f, p1 = 0.f;
#pragma unroll
        for (int nt = 0; nt < 8; nt++) {
            const size_t row0 = (size_t)(bm + wm * 32 + mt * 16 + g);
            const size_t col  = (size_t)(bn + wn * 64 + nt * 8 + 2 * t);
            if (EPI == 2) {
                hf e0 = __float2half_rn(__expf(acc[mt][nt][0] * (1.f / 32.f)));
                hf e1 = __float2half_rn(__expf(acc[mt][nt][1] * (1.f / 32.f)));
                hf e2 = __float2half_rn(__expf(acc[mt][nt][2] * (1.f / 32.f)));
                hf e3 = __float2half_rn(__expf(acc[mt][nt][3] * (1.f / 32.f)));
                p0 += __half2float(e0) + __half2float(e1);
                p1 += __half2float(e2) + __half2float(e3);
                *(uint32_t*)(Ch + row0 * ldc + col)       = packh(e0, e1);
                *(uint32_t*)(Ch + (row0 + 8) * ldc + col) = packh(e2, e3);
            } else if (EPI == 3) {
                const float i0 = invrs[row0], i1 = invrs[row0 + 8];
                *(float2*)(Cf + row0 * ldc + col) =
                    make_float2(acc[mt][nt][0] * i0, acc[mt][nt][1] * i0);
                *(float2*)(Cf + (row0 + 8) * ldc + col) =
                    make_float2(acc[mt][nt][2] * i1, acc[mt][nt][3] * i1);
            } else { // EPI == 4
                *(uint32_t*)(Ch + row0 * ldc + col) =
                    packh(__float2half_rn(acc[mt][nt][0]), __float2half_rn(acc[mt][nt][1]));
                *(uint32_t*)(Ch + (row0 + 8) * ldc + col) =
                    packh(__float2half_rn(acc[mt][nt][2]), __float2half_rn(acc[mt][nt][3]));
            }
        }
        if (EPI == 2) {
            p0 += __shfl_xor_sync(0xffffffffu, p0, 1);
            p0 += __shfl_xor_sync(0xffffffffu, p0, 2);
            p1 += __shfl_xor_sync(0xffffffffu, p1, 1);
            p1 += __shfl_xor_sync(0xffffffffu, p1, 2);
            if (t == 0) {
                const int row0 = bm + wm * 32 + mt * 16 + g;
                part[(size_t)row0 * 32 + bx * 2 + wn]       = p0;
                part[(size_t)(row0 + 8) * 32 + bx * 2 + wn] = p1;
            }
        }
    }
}

// ---------------------------------------------------------------------------
// both-split 3-MMA body (vp^T), single fp16 out.
// ---------------------------------------------------------------------------
__device__ __forceinline__ void gemm128_split_body(
    char* smem,
    const hf* __restrict__ Ah, const hf* __restrict__ Al,
    const hf* __restrict__ Bh, const hf* __restrict__ Bl,
    hf* __restrict__ Ch,
    int K, size_t lda, size_t ldb, size_t ldc, int bm, int bn)
{
    const uint32_t sbase = smem_u32(smem);
    const int tid = threadIdx.x;
    const int wid = tid >> 5, lane = tid & 31;
    const int wm = wid >> 1, wn = wid & 1;
    const int grp = lane >> 3, wi = lane & 7;
    const uint32_t xw = (uint32_t)wi << 4;
    const uint32_t aRow = (uint32_t)(wm * 32 + (grp & 1) * 8 + wi) * 128;
    const uint32_t bRow = (uint32_t)(wn * 64 + (grp >> 1) * 8 + wi) * 128;

    float acc[2][8][4];
#pragma unroll
    for (int i = 0; i < 2; i++)
#pragma unroll
        for (int j = 0; j < 8; j++)
#pragma unroll
            for (int r = 0; r < 4; r++) acc[i][j][r] = 0.f;

    auto fill_stage = [&](int s, int kt) {
        const uint32_t st = sbase + (uint32_t)s * STAGE_PROJ;
        fill_split(st,         Ah, Al, lda, bm, kt * 32, tid);
        fill_split(st + SUB16, Bh, Bl, ldb, bn, kt * 32, tid);
        cp_commit();
    };

    const int NT = K / 32;
    fill_stage(0, 0);
    fill_stage(1, 1);

    for (int kt = 0; kt < NT; kt++) {
        if (kt + 1 < NT) cp_wait<1>(); else cp_wait<0>();
        __syncthreads();
        if (kt + 2 < NT) fill_stage((kt + 2) % 3, kt + 2);

        const uint32_t st = sbase + (uint32_t)(kt % 3) * STAGE_PROJ;
#pragma unroll
        for (int kk = 0; kk < 2; kk++) {
            uint32_t ah[2][4], al[2][4];
            const uint32_t ak = ((uint32_t)(kk * 2 + (grp >> 1)) << 4) ^ xw;
#pragma unroll
            for (int mt = 0; mt < 2; mt++) {
                const uint32_t ao = st + aRow + (uint32_t)mt * 2048 + ak;
                ldsm4(ah[mt], ao);
                ldsm4(al[mt], ao ^ 64u);
            }
            const uint32_t bk = ((uint32_t)(kk * 2 + (grp & 1)) << 4) ^ xw;
#pragma unroll
            for (int np = 0; np < 4; np++) {
                uint32_t bh[4], bl[4];
                const uint32_t bo = st + SUB16 + bRow + (uint32_t)np * 2048 + bk;
                ldsm4(bh, bo);
                ldsm4(bl, bo ^ 64u);
#pragma unroll
                for (int mt = 0; mt < 2; mt++)
#pragma unroll
                    for (int half = 0; half < 2; half++) {
                        const int nt = np * 2 + half;
                        const int h = half * 2;
                        mma_fp16(acc[mt][nt], ah[mt], bh[h], bh[h + 1]);
                        mma_fp16(acc[mt][nt], ah[mt], bl[h], bl[h + 1]);
                        mma_fp16(acc[mt][nt], al[mt], bh[h], bh[h + 1]);
                    }
            }
        }
    }

    const int g = lane >> 2, t = lane & 3;
#pragma unroll
    for (int mt = 0; mt < 2; mt++)
#pragma unroll
        for (int nt = 0; nt < 8; nt++) {
            const size_t row0 = (size_t)(bm + wm * 32 + mt * 16 + g);
            const size_t col  = (size_t)(bn + wn * 64 + nt * 8 + 2 * t);
            *(uint32_t*)(Ch + row0 * ldc + col) =
                packh(__float2half_rn(acc[mt][nt][0]), __float2half_rn(acc[mt][nt][1]));
            *(uint32_t*)(Ch + (row0 + 8) * ldc + col) =
                packh(__float2half_rn(acc[mt][nt][2]), __float2half_rn(acc[mt][nt][3]));
        }
}

// ---------------------------------------------------------------------------
// 64x64 both-split 3-MMA (M'), single fp16 out.
// ---------------------------------------------------------------------------
constexpr int SUB64 = 64 * 128;
constexpr int STAGE64 = 2 * SUB64;
constexpr int GSMEM64 = 3 * STAGE64;   // 48 KB

__device__ __forceinline__ void fill64(uint32_t dst, const hf* __restrict__ H,
                                       const hf* __restrict__ L,
                                       size_t ld, int rowbase, int k0, int tid) {
#pragma unroll
    for (int p = 0; p < 2; p++) {
        int idx = tid + p * 256;
        int r = idx >> 3, c = idx & 7;
        uint32_t off = (uint32_t)(r * 128) + ((((uint32_t)c) ^ ((uint32_t)r & 7)) << 4);
        const hf* src = (c < 4)
            ? H + (size_t)(rowbase + r) * ld + k0 + c * 8
            : L + (size_t)(rowbase + r) * ld + k0 + (c - 4) * 8;
        cp16s(dst + off, src);
    }
}

__device__ __forceinline__ void gemm64_body(
    char* smem,
    const hf* __restrict__ Ah, const hf* __restrict__ Al,
    const hf* __restrict__ Bh, const hf* __restrict__ Bl,
    hf* __restrict__ Cs, int K, size_t ld, int bm, int bn)
{
    const uint32_t sbase = smem_u32(smem);
    const int tid = threadIdx.x;
    const int wid = tid >> 5, lane = tid & 31;
    const int wm = wid >> 1, wn = wid & 1;
    const int grp = lane >> 3, wi = lane & 7;
    const uint32_t xw = (uint32_t)wi << 4;
    const uint32_t aRow = (uint32_t)(wm * 16 + (grp & 1) * 8 + wi) * 128;
    const uint32_t bRow = (uint32_t)(wn * 32 + (grp >> 1) * 8 + wi) * 128;

    float acc[4][4];
#pragma unroll
    for (int j = 0; j < 4; j++)
#pragma unroll
        for (int r = 0; r < 4; r++) acc[j][r] = 0.f;

    auto fill_stage = [&](int s, int kt) {
        const uint32_t st = sbase + (uint32_t)s * STAGE64;
        fill64(st,         Ah, Al, ld, bm, kt * 32, tid);
        fill64(st + SUB64, Bh, Bl, ld, bn, kt * 32, tid);
        cp_commit();
    };

    const int NT = K / 32;
    fill_stage(0, 0);
    fill_stage(1, 1);

    for (int kt = 0; kt < NT; kt++) {
        if (kt + 1 < NT) cp_wait<1>(); else cp_wait<0>();
        __syncthreads();
        if (kt + 2 < NT) fill_stage((kt + 2) % 3, kt + 2);

        const uint32_t st = sbase + (uint32_t)(kt % 3) * STAGE64;
#pragma unroll
        for (int kk = 0; kk < 2; kk++) {
            uint32_t ah[4], al[4];
            const uint32_t ak = ((uint32_t)(kk * 2 + (grp >> 1)) << 4) ^ xw;
            const uint32_t ao = st + aRow + ak;
            ldsm4(ah, ao);
            ldsm4(al, ao ^ 64u);
            const uint32_t bk = ((uint32_t)(kk * 2 + (grp & 1)) << 4) ^ xw;
#pragma unroll
            for (int np = 0; np < 2; np++) {
                uint32_t bh[4], bl[4];
                const uint32_t bo = st + SUB64 + bRow + (uint32_t)np * 2048 + bk;
                ldsm4(bh, bo);
                ldsm4(bl, bo ^ 64u);
#pragma unroll
                for (int half = 0; half < 2; half++) {
                    const int nt = np * 2 + half;
                    const int h = half * 2;
                    mma_fp16(acc[nt], ah, bh[h], bh[h + 1]);
                    mma_fp16(acc[nt], ah, bl[h], bl[h + 1]);
                    mma_fp16(acc[nt], al, bh[h], bh[h + 1]);
                }
            }
        }
    }

    const int g = lane >> 2, t = lane & 3;
#pragma unroll
    for (int nt = 0; nt < 4; nt++) {
        const size_t row0 = (size_t)(bm + wm * 16 + g);
        const size_t col  = (size_t)(bn + wn * 32 + nt * 8 + 2 * t);
        *(uint32_t*)(Cs + row0 * ld + col) =
            packh(__float2half_rn(acc[nt][0]), __float2half_rn(acc[nt][1]));
        *(uint32_t*)(Cs + (row0 + 8) * ld + col) =
            packh(__float2half_rn(acc[nt][2]), __float2half_rn(acc[nt][3]));
    }
}

// ---------------------------------------------------------------------------
// prep1: transpose+split wq, wk (fp16)
// ---------------------------------------------------------------------------
__global__ __launch_bounds__(256)
void prep1_kernel(const float* __restrict__ wq, hf* __restrict__ wqth, hf* __restrict__ wqtl,
                  const float* __restrict__ wk, hf* __restrict__ wkth, hf* __restrict__ wktl)
{
    __shared__ float tile[32][33];
    const int tb = blockIdx.x & 1023;
    const float* x = (blockIdx.x < 1024) ? wq : wk;
    hf* h = (blockIdx.x < 1024) ? wqth : wkth;
    hf* l = (blockIdx.x < 1024) ? wqtl : wktl;
    const int tx = threadIdx.x & 31, ty = threadIdx.x >> 5;
    const int r0 = (tb >> 5) * 32, c0 = (tb & 31) * 32;
#pragma unroll
    for (int i = 0; i < 4; i++)
        tile[ty + i * 8][tx] = x[(size_t)(r0 + ty + i * 8) * D_ + c0 + tx];
    __syncthreads();
#pragma unroll
    for (int i = 0; i < 4; i++) {
        float vv = tile[tx][ty + i * 8];
        hf hh, ll;
        split2(vv, hh, ll);
        h[(size_t)(c0 + ty + i * 8) * D_ + r0 + tx] = hh;
        l[(size_t)(c0 + ty + i * 8) * D_ + r0 + tx] = ll;
    }
}

// ---------------------------------------------------------------------------
// prep2: [0,256) M' 64x64; then q single, k single, v split, wv split.
// ---------------------------------------------------------------------------
__device__ __forceinline__ void split_block(const float* __restrict__ x,
                                            hf* __restrict__ h, hf* __restrict__ l,
                                            size_t bi) {
    const float4* x4 = (const float4*)x;
    uint2* h2 = (uint2*)h;
    uint2* l2 = (uint2*)l;
    const size_t base = bi * 2048 + threadIdx.x;
#pragma unroll
    for (int j = 0; j < 8; j++) {
        float4 vv = x4[base + j * 256];
        hf h0, l0, h1, l1, h2b, l2b, h3, l3;
        split2(vv.x, h0, l0); split2(vv.y, h1, l1);
        split2(vv.z, h2b, l2b); split2(vv.w, h3, l3);
        h2[base + j * 256] = make_uint2(packh(h0, h1), packh(h2b, h3));
        l2[base + j * 256] = make_uint2(packh(l0, l1), packh(l2b, l3));
    }
}
__device__ __forceinline__ void single_conv_block(const float* __restrict__ x,
                                                  hf* __restrict__ h, size_t bi) {
    const float4* x4 = (const float4*)x;
    uint2* h2 = (uint2*)h;
    const size_t base = bi * 2048 + threadIdx.x;
#pragma unroll
    for (int j = 0; j < 8; j++) {
        float4 vv = x4[base + j * 256];
        h2[base + j * 256] = make_uint2(
            packh(__float2half_rn(vv.x), __float2half_rn(vv.y)),
            packh(__float2half_rn(vv.z), __float2half_rn(vv.w)));
    }
}

__global__ __launch_bounds__(256, 2)
void prep2_kernel(const hf* __restrict__ wkth, const hf* __restrict__ wktl,
                  const hf* __restrict__ wqth, const hf* __restrict__ wqtl,
                  hf* __restrict__ ms,
                  const float* __restrict__ q, hf* __restrict__ qs,
                  const float* __restrict__ k, hf* __restrict__ ks,
                  const float* __restrict__ v, hf* __restrict__ vh, hf* __restrict__ vl,
                  const float* __restrict__ wv, hf* __restrict__ wvh, hf* __restrict__ wvl)
{
    extern __shared__ char smem[];
    const int bx = blockIdx.x;
    if (bx < 256) {
        // M'[e,d] = sum_o WkT[e,o] * WqT[d,o]
        gemm64_body(smem, wkth, wktl, wqth, wqtl, ms,
                    D_, D_, (bx >> 4) * 64, (bx & 15) * 64);
    } else {
        int b = bx - 256;
        if (b < 1024)       single_conv_block(q, qs, (size_t)b);
        else if (b < 2048)  single_conv_block(k, ks, (size_t)(b - 1024));
        else if (b < 3072)  split_block(v, vh, vl, (size_t)(b - 2048));
        else                split_block(wv, wvh, wvl, (size_t)(b - 3072));
    }
}

// ---------------------------------------------------------------------------
// dualproj: qM single 1-MMA (512 blocks) + vp^T split 3-MMA (512 blocks)
// ---------------------------------------------------------------------------
__global__ __launch_bounds__(256, 2)
void dualproj_kernel(const hf* qs, const hf* ms, hf* qms,
                     const hf* wvh, const hf* wvl, const hf* vh, const hf* vl,
                     hf* vts)
{
    extern __shared__ char smem[];
    int bx = blockIdx.x;
    if (bx < 512) {
        // qM[i,e] = sum_d q[i,d] * M'[e,d]
        gemm128_ss_body<4>(smem, qs, ms, D_, D_, D_, qms, nullptr, D_,
                           nullptr, nullptr, (bx >> 3) * 128, (bx & 7) * 128, 0);
    } else {
        bx -= 512;
        gemm128_split_body(smem, wvh, wvl, vh, vl, vts,
                           D_, D_, D_, MS_, (bx >> 6) * 128, (bx & 63) * 128);
    }
}

// scores: e = rn(exp(qM k^T / 32)) + row partials
__global__ __launch_bounds__(256, 2)
void scores_kernel(const hf* __restrict__ qms, const hf* __restrict__ ks,
                   hf* __restrict__ e, float* __restrict__ part)
{
    extern __shared__ char smem[];
    const size_t zq = (size_t)blockIdx.z * S_ * D_;
    gemm128_ss_body<2>(smem, qms + zq, ks + zq, D_, D_, D_,
                       e + (size_t)blockIdx.z * S_ * S_, nullptr, S_,
                       part + (size_t)blockIdx.z * S_ * 32, nullptr,
                       blockIdx.y * 128, blockIdx.x * 128, blockIdx.x);
}

__global__ __launch_bounds__(256)
void reduce_inv_kernel(const float* __restrict__ part, float* __restrict__ invrs)
{
    const int row = blockIdx.x * 8 + (threadIdx.x >> 5);
    const int lane = threadIdx.x & 31;
    float vv = part[(size_t)row * 32 + lane];
#pragma unroll
    for (int off = 16; off > 0; off >>= 1)
        vv += __shfl_xor_sync(0xffffffffu, vv, off);
    if (lane == 0) invrs[row] = 1.f / vv;
}

// pv: out = diag(invrs) e vp
__global__ __launch_bounds__(256, 2)
void pv_kernel(const hf* __restrict__ e, const hf* __restrict__ vts,
               float* __restrict__ out, const float* __restrict__ invrs)
{
    extern __shared__ char smem[];
    gemm128_ss_body<3>(smem, e + (size_t)blockIdx.z * S_ * S_,
                       vts + (size_t)blockIdx.z * S_, S_, MS_, S_,
                       nullptr, out + (size_t)blockIdx.z * S_ * D_, D_,
                       nullptr, invrs + (size_t)blockIdx.z * S_,
                       blockIdx.y * 128, blockIdx.x * 128, 0);
}

// ---------------------------------------------------------------------------
extern "C" void kernel_launch(void* const* d_in, const int* in_sizes, int n_in,
                              void* d_out, int out_size)
{
    const float* q  = (const float*)d_in[0];
    const float* k  = (const float*)d_in[1];
    const float* v  = (const float*)d_in[2];
    const float* wq = (const float*)d_in[3];
    const float* wk = (const float*)d_in[4];
    const float* wv = (const float*)d_in[5];
    float* out = (float*)d_out;

    hf *qs, *ks, *vh, *vl;
    hf *wqth, *wqtl, *wkth, *wktl, *wvh, *wvl;
    hf *ms, *qms, *vts, *e;
    float *part, *invrs;
    cudaGetSymbolAddress((void**)&qs, g_qs);     cudaGetSymbolAddress((void**)&ks, g_ks);
    cudaGetSymbolAddress((void**)&vh, g_vh);     cudaGetSymbolAddress((void**)&vl, g_vl);
    cudaGetSymbolAddress((void**)&wqth, g_wqth); cudaGetSymbolAddress((void**)&wqtl, g_wqtl);
    cudaGetSymbolAddress((void**)&wkth, g_wkth); cudaGetSymbolAddress((void**)&wktl, g_wktl);
    cudaGetSymbolAddress((void**)&wvh, g_wvh);   cudaGetSymbolAddress((void**)&wvl, g_wvl);
    cudaGetSymbolAddress((void**)&ms, g_ms);     cudaGetSymbolAddress((void**)&qms, g_qms);
    cudaGetSymbolAddress((void**)&vts, g_vts);   cudaGetSymbolAddress((void**)&e, g_e);
    cudaGetSymbolAddress((void**)&part, g_part); cudaGetSymbolAddress((void**)&invrs, g_invrs);

    cudaFuncSetAttribute(prep2_kernel,    cudaFuncAttributeMaxDynamicSharedMemorySize, GSMEM64);
    cudaFuncSetAttribute(dualproj_kernel, cudaFuncAttributeMaxDynamicSharedMemorySize, GSMEM_PROJ);
    cudaFuncSetAttribute(scores_kernel,   cudaFuncAttributeMaxDynamicSharedMemorySize, GSMEM_SS);
    cudaFuncSetAttribute(pv_kernel,       cudaFuncAttributeMaxDynamicSharedMemorySize, GSMEM_SS);

    // 1) transpose+split wq, wk
    prep1_kernel<<<2048, 256>>>(wq, wqth, wqtl, wk, wkth, wktl);

    // 2) M' (256 blocks) + q/k single converts + v/wv splits
    prep2_kernel<<<256 + 2 * 1024 + 1024 + 128, 256, GSMEM64>>>(
        wkth, wktl, wqth, wqtl, ms,
        q, qs, k, ks, v, vh, vl, wv, wvh, wvl);

    // 3) qM = q M'^T (single, 1-MMA) and vp^T = Wv v^T (split, 3-MMA)
    dualproj_kernel<<<1024, 256, GSMEM_PROJ>>>(qs, ms, qms, wvh, wvl, vh, vl, vts);

    // 4) e = exp(qM k^T / 32) + row partials
    dim3 gs(16, 16, B_);
    scores_kernel<<<gs, 256, GSMEM_SS>>>(qms, ks, e, part);

    // 5) invrs = 1 / rowsum
    reduce_inv_kernel<<<MS_ / 8, 256>>>(part, invrs);

    // 6) out = diag(invrs) e vp
    dim3 go(8, 16, B_);
    pv_kernel<<<go, 256, GSMEM_SS>>>(e, vts, out, invrs);
}

// round 9
// speedup vs baseline: 3.1465x; 1.2459x over previous
#include <cuda_runtime.h>
#include <cuda_fp16.h>
#include <math.h>
#include <cstdint>

// ---------------------------------------------------------------------------
// AttentionHead B=4, S=2048, D=1024 — mma.sync fp16 tiered precision v3.
// M' = Wk^T Wq (3-MMA from weight splits, rounded single).
// qM = q x M' (1-MMA). scores = qM x k (1-MMA). vp^T = Wv x v (1-MMA).
// PV = e x vp (1-MMA). Softmax fused: scores epilogue exp+partials;
// PV start computes 1/rowsum in smem, epilogue scales.
// ---------------------------------------------------------------------------

#define B_ 4
#define S_ 2048
#define D_ 1024
#define MS_ (B_ * S_)   // 8192
typedef __half hf;

// ---- scratch ----
__device__ __align__(16) hf g_qs [(size_t)MS_ * D_];
__device__ __align__(16) hf g_ks [(size_t)MS_ * D_];
__device__ __align__(16) hf g_vs [(size_t)MS_ * D_];
__device__ __align__(16) hf g_wqth[(size_t)D_ * D_];
__device__ __align__(16) hf g_wqtl[(size_t)D_ * D_];
__device__ __align__(16) hf g_wkth[(size_t)D_ * D_];
__device__ __align__(16) hf g_wktl[(size_t)D_ * D_];
__device__ __align__(16) hf g_wvs [(size_t)D_ * D_];
__device__ __align__(16) hf g_ms  [(size_t)D_ * D_];
__device__ __align__(16) hf g_qms [(size_t)MS_ * D_];
__device__ __align__(16) hf g_vts [(size_t)D_ * MS_];  // vp^T [D, MS]
__device__ __align__(16) hf g_e   [(size_t)B_ * S_ * S_];
__device__ __align__(16) float g_part [(size_t)MS_ * 32];

// ---- helpers ----
__device__ __forceinline__ uint32_t smem_u32(const void* p) {
    uint32_t a;
    asm("{ .reg .u64 t; cvta.to.shared.u64 t, %1; cvt.u32.u64 %0, t; }" : "=r"(a) : "l"(p));
    return a;
}
__device__ __forceinline__ void cp16s(uint32_t dst, const void* src) {
    asm volatile("cp.async.cg.shared.global [%0], [%1], 16;\n" :: "r"(dst), "l"(src));
}
__device__ __forceinline__ void cp_commit() { asm volatile("cp.async.commit_group;\n"); }
template <int N> __device__ __forceinline__ void cp_wait() {
    asm volatile("cp.async.wait_group %0;\n" :: "n"(N));
}
__device__ __forceinline__ void ldsm4(uint32_t (&r)[4], uint32_t addr) {
    asm volatile("ldmatrix.sync.aligned.m8n8.x4.shared.b16 {%0,%1,%2,%3}, [%4];"
                 : "=r"(r[0]), "=r"(r[1]), "=r"(r[2]), "=r"(r[3]) : "r"(addr));
}
__device__ __forceinline__ void mma_fp16(float (&d)[4], const uint32_t (&a)[4],
                                         uint32_t b0, uint32_t b1) {
    asm volatile(
        "mma.sync.aligned.m16n8k16.row.col.f32.f16.f16.f32 "
        "{%0,%1,%2,%3}, {%4,%5,%6,%7}, {%8,%9}, {%0,%1,%2,%3};\n"
        : "+f"(d[0]), "+f"(d[1]), "+f"(d[2]), "+f"(d[3])
        : "r"(a[0]), "r"(a[1]), "r"(a[2]), "r"(a[3]), "r"(b0), "r"(b1));
}
__device__ __forceinline__ void split2(float x, hf& h, hf& l) {
    h = __float2half_rn(x);
    l = __float2half_rn(x - __half2float(h));
}
__device__ __forceinline__ uint32_t packh(hf a, hf b) {
    __half2 p = __halves2half2(a, b);
    return *(uint32_t*)&p;
}

// ---------------------------------------------------------------------------
constexpr int SUB16 = 128 * 128;           // 16 KB
constexpr int STG_SS = 2 * SUB16;          // A single + B single (BK=64) = 32 KB
constexpr int GSMEM_SS = 3 * STG_SS;       // 96 KB
constexpr int GSMEM_PV = GSMEM_SS + 512;   // + smem invrs

__device__ __forceinline__ void fill_single(uint32_t dst, const hf* __restrict__ X,
                                            size_t ld, int rowbase, int k0, int tid) {
#pragma unroll
    for (int p = 0; p < 4; p++) {
        int idx = tid + p * 256;
        int r = idx >> 3, c = idx & 7;
        uint32_t off = (uint32_t)(r * 128) + ((((uint32_t)c) ^ ((uint32_t)r & 7)) << 4);
        cp16s(dst + off, X + (size_t)(rowbase + r) * ld + k0 + c * 8);
    }
}

// ---------------------------------------------------------------------------
// single x single 1-MMA body, BK=64.
// EPI 2: e=rn(exp(acc/32)) -> Ch + row partials. EPI 3: fp32 * invrs[row].
// EPI 4: single fp16 out.
// ---------------------------------------------------------------------------
template <int EPI>
__device__ __forceinline__ void gemm128_ss_body(
    char* smem, const hf* __restrict__ A, const hf* __restrict__ Bx,
    size_t lda, size_t ldb, int K,
    hf* __restrict__ Ch, float* __restrict__ Cf, size_t ldc,
    float* __restrict__ part, const float* __restrict__ invrs,
    int bm, int bn, int bx)
{
    const uint32_t sbase = smem_u32(smem);
    const int tid = threadIdx.x;
    const int wid = tid >> 5, lane = tid & 31;
    const int wm = wid >> 1, wn = wid & 1;
    const int grp = lane >> 3, wi = lane & 7;
    const uint32_t xw = (uint32_t)wi << 4;
    const uint32_t aRow = (uint32_t)(wm * 32 + (grp & 1) * 8 + wi) * 128;
    const uint32_t bRow = (uint32_t)(wn * 64 + (grp >> 1) * 8 + wi) * 128;

    float acc[2][8][4];
#pragma unroll
    for (int i = 0; i < 2; i++)
#pragma unroll
        for (int j = 0; j < 8; j++)
#pragma unroll
            for (int r = 0; r < 4; r++) acc[i][j][r] = 0.f;

    auto fill_stage = [&](int s, int kt) {
        const uint32_t st = sbase + (uint32_t)s * STG_SS;
        const int k0 = kt * 64;
        fill_single(st,         A,  lda, bm, k0, tid);
        fill_single(st + SUB16, Bx, ldb, bn, k0, tid);
        cp_commit();
    };

    const int NT = K / 64;
    fill_stage(0, 0);
    fill_stage(1, 1);

    for (int kt = 0; kt < NT; kt++) {
        if (kt + 1 < NT) cp_wait<1>(); else cp_wait<0>();
        __syncthreads();
        if (kt + 2 < NT) fill_stage((kt + 2) % 3, kt + 2);

        const uint32_t st = sbase + (uint32_t)(kt % 3) * STG_SS;
#pragma unroll
        for (int kk = 0; kk < 4; kk++) {
            uint32_t aa[2][4];
            const uint32_t ak = ((uint32_t)(kk * 2 + (grp >> 1)) << 4) ^ xw;
#pragma unroll
            for (int mt = 0; mt < 2; mt++)
                ldsm4(aa[mt], st + aRow + (uint32_t)mt * 2048 + ak);
            const uint32_t bk = ((uint32_t)(kk * 2 + (grp & 1)) << 4) ^ xw;
#pragma unroll
            for (int np = 0; np < 4; np++) {
                uint32_t bb[4];
                ldsm4(bb, st + SUB16 + bRow + (uint32_t)np * 2048 + bk);
#pragma unroll
                for (int mt = 0; mt < 2; mt++)
#pragma unroll
                    for (int half = 0; half < 2; half++)
                        mma_fp16(acc[mt][np * 2 + half], aa[mt],
                                 bb[half * 2], bb[half * 2 + 1]);
            }
        }
    }

    const int g = lane >> 2, t = lane & 3;
#pragma unroll
    for (int mt = 0; mt < 2; mt++) {
        float p0 = 0.f, p1 = 0.f;
#pragma unroll
        for (int nt = 0; nt < 8; nt++) {
            const size_t row0 = (size_t)(bm + wm * 32 + mt * 16 + g);
            const size_t col  = (size_t)(bn + wn * 64 + nt * 8 + 2 * t);
            if (EPI == 2) {
                hf e0 = __float2half_rn(__expf(acc[mt][nt][0] * (1.f / 32.f)));
                hf e1 = __float2half_rn(__expf(acc[mt][nt][1] * (1.f / 32.f)));
                hf e2 = __float2half_rn(__expf(acc[mt][nt][2] * (1.f / 32.f)));
                hf e3 = __float2half_rn(__expf(acc[mt][nt][3] * (1.f / 32.f)));
                p0 += __half2float(e0) + __half2float(e1);
                p1 += __half2float(e2) + __half2float(e3);
                *(uint32_t*)(Ch + row0 * ldc + col)       = packh(e0, e1);
                *(uint32_t*)(Ch + (row0 + 8) * ldc + col) = packh(e2, e3);
            } else if (EPI == 3) {
                const float i0 = invrs[row0], i1 = invrs[row0 + 8];
                *(float2*)(Cf + row0 * ldc + col) =
                    make_float2(acc[mt][nt][0] * i0, acc[mt][nt][1] * i0);
                *(float2*)(Cf + (row0 + 8) * ldc + col) =
                    make_float2(acc[mt][nt][2] * i1, acc[mt][nt][3] * i1);
            } else { // EPI == 4
                *(uint32_t*)(Ch + row0 * ldc + col) =
                    packh(__float2half_rn(acc[mt][nt][0]), __float2half_rn(acc[mt][nt][1]));
                *(uint32_t*)(Ch + (row0 + 8) * ldc + col) =
                    packh(__float2half_rn(acc[mt][nt][2]), __float2half_rn(acc[mt][nt][3]));
            }
        }
        if (EPI == 2) {
            p0 += __shfl_xor_sync(0xffffffffu, p0, 1);
            p0 += __shfl_xor_sync(0xffffffffu, p0, 2);
            p1 += __shfl_xor_sync(0xffffffffu, p1, 1);
            p1 += __shfl_xor_sync(0xffffffffu, p1, 2);
            if (t == 0) {
                const int row0 = bm + wm * 32 + mt * 16 + g;
                part[(size_t)row0 * 32 + bx * 2 + wn]       = p0;
                part[(size_t)(row0 + 8) * 32 + bx * 2 + wn] = p1;
            }
        }
    }
}

// ---------------------------------------------------------------------------
// 64x64 both-split 3-MMA (M'), single fp16 out.
// ---------------------------------------------------------------------------
constexpr int SUB64 = 64 * 128;
constexpr int STAGE64 = 2 * SUB64;
constexpr int GSMEM64 = 3 * STAGE64;   // 48 KB

__device__ __forceinline__ void fill64(uint32_t dst, const hf* __restrict__ H,
                                       const hf* __restrict__ L,
                                       size_t ld, int rowbase, int k0, int tid) {
#pragma unroll
    for (int p = 0; p < 2; p++) {
        int idx = tid + p * 256;
        int r = idx >> 3, c = idx & 7;
        uint32_t off = (uint32_t)(r * 128) + ((((uint32_t)c) ^ ((uint32_t)r & 7)) << 4);
        const hf* src = (c < 4)
            ? H + (size_t)(rowbase + r) * ld + k0 + c * 8
            : L + (size_t)(rowbase + r) * ld + k0 + (c - 4) * 8;
        cp16s(dst + off, src);
    }
}

__device__ __forceinline__ void gemm64_body(
    char* smem,
    const hf* __restrict__ Ah, const hf* __restrict__ Al,
    const hf* __restrict__ Bh, const hf* __restrict__ Bl,
    hf* __restrict__ Cs, int K, size_t ld, int bm, int bn)
{
    const uint32_t sbase = smem_u32(smem);
    const int tid = threadIdx.x;
    const int wid = tid >> 5, lane = tid & 31;
    const int wm = wid >> 1, wn = wid & 1;
    const int grp = lane >> 3, wi = lane & 7;
    const uint32_t xw = (uint32_t)wi << 4;
    const uint32_t aRow = (uint32_t)(wm * 16 + (grp & 1) * 8 + wi) * 128;
    const uint32_t bRow = (uint32_t)(wn * 32 + (grp >> 1) * 8 + wi) * 128;

    float acc[4][4];
#pragma unroll
    for (int j = 0; j < 4; j++)
#pragma unroll
        for (int r = 0; r < 4; r++) acc[j][r] = 0.f;

    auto fill_stage = [&](int s, int kt) {
        const uint32_t st = sbase + (uint32_t)s * STAGE64;
        fill64(st,         Ah, Al, ld, bm, kt * 32, tid);
        fill64(st + SUB64, Bh, Bl, ld, bn, kt * 32, tid);
        cp_commit();
    };

    const int NT = K / 32;
    fill_stage(0, 0);
    fill_stage(1, 1);

    for (int kt = 0; kt < NT; kt++) {
        if (kt + 1 < NT) cp_wait<1>(); else cp_wait<0>();
        __syncthreads();
        if (kt + 2 < NT) fill_stage((kt + 2) % 3, kt + 2);

        const uint32_t st = sbase + (uint32_t)(kt % 3) * STAGE64;
#pragma unroll
        for (int kk = 0; kk < 2; kk++) {
            uint32_t ah[4], al[4];
            const uint32_t ak = ((uint32_t)(kk * 2 + (grp >> 1)) << 4) ^ xw;
            const uint32_t ao = st + aRow + ak;
            ldsm4(ah, ao);
            ldsm4(al, ao ^ 64u);
            const uint32_t bk = ((uint32_t)(kk * 2 + (grp & 1)) << 4) ^ xw;
#pragma unroll
            for (int np = 0; np < 2; np++) {
                uint32_t bh[4], bl[4];
                const uint32_t bo = st + SUB64 + bRow + (uint32_t)np * 2048 + bk;
                ldsm4(bh, bo);
                ldsm4(bl, bo ^ 64u);
#pragma unroll
                for (int half = 0; half < 2; half++) {
                    const int nt = np * 2 + half;
                    const int h = half * 2;
                    mma_fp16(acc[nt], ah, bh[h], bh[h + 1]);
                    mma_fp16(acc[nt], ah, bl[h], bl[h + 1]);
                    mma_fp16(acc[nt], al, bh[h], bh[h + 1]);
                }
            }
        }
    }

    const int g = lane >> 2, t = lane & 3;
#pragma unroll
    for (int nt = 0; nt < 4; nt++) {
        const size_t row0 = (size_t)(bm + wm * 16 + g);
        const size_t col  = (size_t)(bn + wn * 32 + nt * 8 + 2 * t);
        *(uint32_t*)(Cs + row0 * ld + col) =
            packh(__float2half_rn(acc[nt][0]), __float2half_rn(acc[nt][1]));
        *(uint32_t*)(Cs + (row0 + 8) * ld + col) =
            packh(__float2half_rn(acc[nt][2]), __float2half_rn(acc[nt][3]));
    }
}

// ---------------------------------------------------------------------------
// prep1: transpose+split wq, wk
// ---------------------------------------------------------------------------
__global__ __launch_bounds__(256)
void prep1_kernel(const float* __restrict__ wq, hf* __restrict__ wqth, hf* __restrict__ wqtl,
                  const float* __restrict__ wk, hf* __restrict__ wkth, hf* __restrict__ wktl)
{
    __shared__ float tile[32][33];
    const int tb = blockIdx.x & 1023;
    const float* x = (blockIdx.x < 1024) ? wq : wk;
    hf* h = (blockIdx.x < 1024) ? wqth : wkth;
    hf* l = (blockIdx.x < 1024) ? wqtl : wktl;
    const int tx = threadIdx.x & 31, ty = threadIdx.x >> 5;
    const int r0 = (tb >> 5) * 32, c0 = (tb & 31) * 32;
#pragma unroll
    for (int i = 0; i < 4; i++)
        tile[ty + i * 8][tx] = x[(size_t)(r0 + ty + i * 8) * D_ + c0 + tx];
    __syncthreads();
#pragma unroll
    for (int i = 0; i < 4; i++) {
        float vv = tile[tx][ty + i * 8];
        hf hh, ll;
        split2(vv, hh, ll);
        h[(size_t)(c0 + ty + i * 8) * D_ + r0 + tx] = hh;
        l[(size_t)(c0 + ty + i * 8) * D_ + r0 + tx] = ll;
    }
}

// ---------------------------------------------------------------------------
// prep2: [0,256) M' 64x64; then q, k, v, wv single converts.
// ---------------------------------------------------------------------------
__device__ __forceinline__ void single_conv_block(const float* __restrict__ x,
                                                  hf* __restrict__ h, size_t bi) {
    const float4* x4 = (const float4*)x;
    uint2* h2 = (uint2*)h;
    const size_t base = bi * 2048 + threadIdx.x;
#pragma unroll
    for (int j = 0; j < 8; j++) {
        float4 vv = x4[base + j * 256];
        h2[base + j * 256] = make_uint2(
            packh(__float2half_rn(vv.x), __float2half_rn(vv.y)),
            packh(__float2half_rn(vv.z), __float2half_rn(vv.w)));
    }
}

__global__ __launch_bounds__(256, 2)
void prep2_kernel(const hf* __restrict__ wkth, const hf* __restrict__ wktl,
                  const hf* __restrict__ wqth, const hf* __restrict__ wqtl,
                  hf* __restrict__ ms,
                  const float* __restrict__ q, hf* __restrict__ qs,
                  const float* __restrict__ k, hf* __restrict__ ks,
                  const float* __restrict__ v, hf* __restrict__ vs,
                  const float* __restrict__ wv, hf* __restrict__ wvs)
{
    extern __shared__ char smem[];
    const int bx = blockIdx.x;
    if (bx < 256) {
        gemm64_body(smem, wkth, wktl, wqth, wqtl, ms,
                    D_, D_, (bx >> 4) * 64, (bx & 15) * 64);
    } else {
        int b = bx - 256;
        if (b < 1024)       single_conv_block(q, qs, (size_t)b);
        else if (b < 2048)  single_conv_block(k, ks, (size_t)(b - 1024));
        else if (b < 3072)  single_conv_block(v, vs, (size_t)(b - 2048));
        else                single_conv_block(wv, wvs, (size_t)(b - 3072));
    }
}

// ---------------------------------------------------------------------------
// dualproj: qM (512 blocks) + vp^T (512 blocks), both single 1-MMA
// ---------------------------------------------------------------------------
__global__ __launch_bounds__(256, 2)
void dualproj_kernel(const hf* qs, const hf* ms, hf* qms,
                     const hf* wvs, const hf* vs, hf* vts)
{
    extern __shared__ char smem[];
    int bx = blockIdx.x;
    if (bx < 512) {
        // qM[i,e] = sum_d q[i,d] * M'[e,d]
        gemm128_ss_body<4>(smem, qs, ms, D_, D_, D_, qms, nullptr, D_,
                           nullptr, nullptr, (bx >> 3) * 128, (bx & 7) * 128, 0);
    } else {
        bx -= 512;
        // vp^T[e,i] = sum_d Wv[e,d] * v[i,d]
        gemm128_ss_body<4>(smem, wvs, vs, D_, D_, D_, vts, nullptr, MS_,
                           nullptr, nullptr, (bx >> 6) * 128, (bx & 63) * 128, 0);
    }
}

// scores: e = rn(exp(qM k^T / 32)) + row partials
__global__ __launch_bounds__(256, 2)
void scores_kernel(const hf* __restrict__ qms, const hf* __restrict__ ks,
                   hf* __restrict__ e, float* __restrict__ part)
{
    extern __shared__ char smem[];
    const size_t zq = (size_t)blockIdx.z * S_ * D_;
    gemm128_ss_body<2>(smem, qms + zq, ks + zq, D_, D_, D_,
                       e + (size_t)blockIdx.z * S_ * S_, nullptr, S_,
                       part + (size_t)blockIdx.z * S_ * 32, nullptr,
                       blockIdx.y * 128, blockIdx.x * 128, blockIdx.x);
}

// pv: computes invrs for its 128 rows into smem, then out = diag(invrs) e vp
__global__ __launch_bounds__(256, 2)
void pv_kernel(const hf* __restrict__ e, const hf* __restrict__ vts,
               float* __restrict__ out, const float* __restrict__ part)
{
    extern __shared__ char smem[];
    float* sInv = (float*)(smem + GSMEM_SS);
    const int bm = blockIdx.y * 128;
    const float* pz = part + (size_t)blockIdx.z * S_ * 32;
    if (threadIdx.x < 128) {
        const float* pr = pz + (size_t)(bm + threadIdx.x) * 32;
        float s = 0.f;
#pragma unroll
        for (int j = 0; j < 32; j++) s += pr[j];
        sInv[threadIdx.x] = 1.f / s;
    }
    __syncthreads();

    gemm128_ss_body<3>(smem, e + (size_t)blockIdx.z * S_ * S_,
                       vts + (size_t)blockIdx.z * S_, S_, MS_, S_,
                       nullptr, out + (size_t)blockIdx.z * S_ * D_, D_,
                       nullptr, sInv - bm,
                       bm, blockIdx.x * 128, 0);
}

// ---------------------------------------------------------------------------
extern "C" void kernel_launch(void* const* d_in, const int* in_sizes, int n_in,
                              void* d_out, int out_size)
{
    const float* q  = (const float*)d_in[0];
    const float* k  = (const float*)d_in[1];
    const float* v  = (const float*)d_in[2];
    const float* wq = (const float*)d_in[3];
    const float* wk = (const float*)d_in[4];
    const float* wv = (const float*)d_in[5];
    float* out = (float*)d_out;

    hf *qs, *ks, *vs, *wvs;
    hf *wqth, *wqtl, *wkth, *wktl;
    hf *ms, *qms, *vts, *e;
    float *part;
    cudaGetSymbolAddress((void**)&qs, g_qs);     cudaGetSymbolAddress((void**)&ks, g_ks);
    cudaGetSymbolAddress((void**)&vs, g_vs);     cudaGetSymbolAddress((void**)&wvs, g_wvs);
    cudaGetSymbolAddress((void**)&wqth, g_wqth); cudaGetSymbolAddress((void**)&wqtl, g_wqtl);
    cudaGetSymbolAddress((void**)&wkth, g_wkth); cudaGetSymbolAddress((void**)&wktl, g_wktl);
    cudaGetSymbolAddress((void**)&ms, g_ms);     cudaGetSymbolAddress((void**)&qms, g_qms);
    cudaGetSymbolAddress((void**)&vts, g_vts);   cudaGetSymbolAddress((void**)&e, g_e);
    cudaGetSymbolAddress((void**)&part, g_part);

    cudaFuncSetAttribute(prep2_kernel,    cudaFuncAttributeMaxDynamicSharedMemorySize, GSMEM64);
    cudaFuncSetAttribute(dualproj_kernel, cudaFuncAttributeMaxDynamicSharedMemorySize, GSMEM_SS);
    cudaFuncSetAttribute(scores_kernel,   cudaFuncAttributeMaxDynamicSharedMemorySize, GSMEM_SS);
    cudaFuncSetAttribute(pv_kernel,       cudaFuncAttributeMaxDynamicSharedMemorySize, GSMEM_PV);

    // 1) transpose+split wq, wk
    prep1_kernel<<<2048, 256>>>(wq, wqth, wqtl, wk, wkth, wktl);

    // 2) M' (256 blocks) + q/k/v/wv single converts
    prep2_kernel<<<256 + 3 * 1024 + 128, 256, GSMEM64>>>(
        wkth, wktl, wqth, wqtl, ms,
        q, qs, k, ks, v, vs, wv, wvs);

    // 3) qM = q M'^T and vp^T = Wv v^T (both single 1-MMA, one launch)
    dualproj_kernel<<<1024, 256, GSMEM_SS>>>(qs, ms, qms, wvs, vs, vts);

    // 4) e = exp(qM k^T / 32) + row partials
    dim3 gs(16, 16, B_);
    scores_kernel<<<gs, 256, GSMEM_SS>>>(qms, ks, e, part);

    // 5) out = diag(1/rowsum) e vp  (invrs computed in-kernel from partials)
    dim3 go(8, 16, B_);
    pv_kernel<<<go, 256, GSMEM_PV>>>(e, vts, out, part);
}

// round 10
// speedup vs baseline: 3.2066x; 1.0191x over previous
#include <cuda_runtime.h>
#include <cuda_fp16.h>
#include <math.h>
#include <cstdint>

// ---------------------------------------------------------------------------
// AttentionHead B=4, S=2048, D=1024 — mma.sync fp16 tiered precision v4.
// Same numerics as v3; main GEMMs now 4 warps/CTA with 64x64 warp tiles
// (halves ldmatrix traffic per MMA; smem crossbar was the binding limit).
// ---------------------------------------------------------------------------

#define B_ 4
#define S_ 2048
#define D_ 1024
#define MS_ (B_ * S_)   // 8192
typedef __half hf;

// ---- scratch ----
__device__ __align__(16) hf g_qs [(size_t)MS_ * D_];
__device__ __align__(16) hf g_ks [(size_t)MS_ * D_];
__device__ __align__(16) hf g_vs [(size_t)MS_ * D_];
__device__ __align__(16) hf g_wqth[(size_t)D_ * D_];
__device__ __align__(16) hf g_wqtl[(size_t)D_ * D_];
__device__ __align__(16) hf g_wkth[(size_t)D_ * D_];
__device__ __align__(16) hf g_wktl[(size_t)D_ * D_];
__device__ __align__(16) hf g_wvs [(size_t)D_ * D_];
__device__ __align__(16) hf g_ms  [(size_t)D_ * D_];
__device__ __align__(16) hf g_qms [(size_t)MS_ * D_];
__device__ __align__(16) hf g_vts [(size_t)D_ * MS_];
__device__ __align__(16) hf g_e   [(size_t)B_ * S_ * S_];
__device__ __align__(16) float g_part [(size_t)MS_ * 32];

// ---- helpers ----
__device__ __forceinline__ uint32_t smem_u32(const void* p) {
    uint32_t a;
    asm("{ .reg .u64 t; cvta.to.shared.u64 t, %1; cvt.u32.u64 %0, t; }" : "=r"(a) : "l"(p));
    return a;
}
__device__ __forceinline__ void cp16s(uint32_t dst, const void* src) {
    asm volatile("cp.async.cg.shared.global [%0], [%1], 16;\n" :: "r"(dst), "l"(src));
}
__device__ __forceinline__ void cp_commit() { asm volatile("cp.async.commit_group;\n"); }
template <int N> __device__ __forceinline__ void cp_wait() {
    asm volatile("cp.async.wait_group %0;\n" :: "n"(N));
}
__device__ __forceinline__ void ldsm4(uint32_t (&r)[4], uint32_t addr) {
    asm volatile("ldmatrix.sync.aligned.m8n8.x4.shared.b16 {%0,%1,%2,%3}, [%4];"
                 : "=r"(r[0]), "=r"(r[1]), "=r"(r[2]), "=r"(r[3]) : "r"(addr));
}
__device__ __forceinline__ void mma_fp16(float (&d)[4], const uint32_t (&a)[4],
                                         uint32_t b0, uint32_t b1) {
    asm volatile(
        "mma.sync.aligned.m16n8k16.row.col.f32.f16.f16.f32 "
        "{%0,%1,%2,%3}, {%4,%5,%6,%7}, {%8,%9}, {%0,%1,%2,%3};\n"
        : "+f"(d[0]), "+f"(d[1]), "+f"(d[2]), "+f"(d[3])
        : "r"(a[0]), "r"(a[1]), "r"(a[2]), "r"(a[3]), "r"(b0), "r"(b1));
}
__device__ __forceinline__ void split2(float x, hf& h, hf& l) {
    h = __float2half_rn(x);
    l = __float2half_rn(x - __half2float(h));
}
__device__ __forceinline__ uint32_t packh(hf a, hf b) {
    __half2 p = __halves2half2(a, b);
    return *(uint32_t*)&p;
}

// ---------------------------------------------------------------------------
constexpr int SUB16 = 128 * 128;           // 16 KB
constexpr int STG_SS = 2 * SUB16;          // 32 KB per stage
constexpr int GSMEM_SS = 3 * STG_SS;       // 96 KB
constexpr int GSMEM_PV = GSMEM_SS + 512;

// 128-thread tile fill (8 chunks per thread)
__device__ __forceinline__ void fill_single(uint32_t dst, const hf* __restrict__ X,
                                            size_t ld, int rowbase, int k0, int tid) {
#pragma unroll
    for (int p = 0; p < 8; p++) {
        int idx = tid + p * 128;
        int r = idx >> 3, c = idx & 7;
        uint32_t off = (uint32_t)(r * 128) + ((((uint32_t)c) ^ ((uint32_t)r & 7)) << 4);
        cp16s(dst + off, X + (size_t)(rowbase + r) * ld + k0 + c * 8);
    }
}

// ---------------------------------------------------------------------------
// single x single 1-MMA body, BK=64, 4 warps, 64x64 warp tile.
// EPI 2: e=rn(exp(acc/32)) -> Ch + row partials. EPI 3: fp32 * invrs[row].
// EPI 4: single fp16 out.
// ---------------------------------------------------------------------------
template <int EPI>
__device__ __forceinline__ void gemm128_ss_body(
    char* smem, const hf* __restrict__ A, const hf* __restrict__ Bx,
    size_t lda, size_t ldb, int K,
    hf* __restrict__ Ch, float* __restrict__ Cf, size_t ldc,
    float* __restrict__ part, const float* __restrict__ invrs,
    int bm, int bn, int bx)
{
    const uint32_t sbase = smem_u32(smem);
    const int tid = threadIdx.x;
    const int wid = tid >> 5, lane = tid & 31;
    const int wm = wid >> 1, wn = wid & 1;       // 2x2 warps, warp tile 64x64
    const int grp = lane >> 3, wi = lane & 7;
    const uint32_t xw = (uint32_t)wi << 4;
    const uint32_t aRow = (uint32_t)(wm * 64 + (grp & 1) * 8 + wi) * 128;
    const uint32_t bRow = (uint32_t)(wn * 64 + (grp >> 1) * 8 + wi) * 128;

    float acc[4][8][4];
#pragma unroll
    for (int i = 0; i < 4; i++)
#pragma unroll
        for (int j = 0; j < 8; j++)
#pragma unroll
            for (int r = 0; r < 4; r++) acc[i][j][r] = 0.f;

    auto fill_stage = [&](int s, int kt) {
        const uint32_t st = sbase + (uint32_t)s * STG_SS;
        const int k0 = kt * 64;
        fill_single(st,         A,  lda, bm, k0, tid);
        fill_single(st + SUB16, Bx, ldb, bn, k0, tid);
        cp_commit();
    };

    const int NT = K / 64;
    fill_stage(0, 0);
    fill_stage(1, 1);

    for (int kt = 0; kt < NT; kt++) {
        if (kt + 1 < NT) cp_wait<1>(); else cp_wait<0>();
        __syncthreads();
        if (kt + 2 < NT) fill_stage((kt + 2) % 3, kt + 2);

        const uint32_t st = sbase + (uint32_t)(kt % 3) * STG_SS;
#pragma unroll
        for (int kk = 0; kk < 4; kk++) {
            uint32_t aa[4][4];
            const uint32_t ak = ((uint32_t)(kk * 2 + (grp >> 1)) << 4) ^ xw;
#pragma unroll
            for (int mt = 0; mt < 4; mt++)
                ldsm4(aa[mt], st + aRow + (uint32_t)mt * 2048 + ak);
            const uint32_t bk = ((uint32_t)(kk * 2 + (grp & 1)) << 4) ^ xw;
#pragma unroll
            for (int np = 0; np < 4; np++) {
                uint32_t bb[4];
                ldsm4(bb, st + SUB16 + bRow + (uint32_t)np * 2048 + bk);
#pragma unroll
                for (int mt = 0; mt < 4; mt++)
#pragma unroll
                    for (int half = 0; half < 2; half++)
                        mma_fp16(acc[mt][np * 2 + half], aa[mt],
                                 bb[half * 2], bb[half * 2 + 1]);
            }
        }
    }

    const int g = lane >> 2, t = lane & 3;
#pragma unroll
    for (int mt = 0; mt < 4; mt++) {
        float p0 = 0.f, p1 = 0.f;
#pragma unroll
        for (int nt = 0; nt < 8; nt++) {
            const size_t row0 = (size_t)(bm + wm * 64 + mt * 16 + g);
            const size_t col  = (size_t)(bn + wn * 64 + nt * 8 + 2 * t);
            if (EPI == 2) {
                hf e0 = __float2half_rn(__expf(acc[mt][nt][0] * (1.f / 32.f)));
                hf e1 = __float2half_rn(__expf(acc[mt][nt][1] * (1.f / 32.f)));
                hf e2 = __float2half_rn(__expf(acc[mt][nt][2] * (1.f / 32.f)));
                hf e3 = __float2half_rn(__expf(acc[mt][nt][3] * (1.f / 32.f)));
                p0 += __half2float(e0) + __half2float(e1);
                p1 += __half2float(e2) + __half2float(e3);
                *(uint32_t*)(Ch + row0 * ldc + col)       = packh(e0, e1);
                *(uint32_t*)(Ch + (row0 + 8) * ldc + col) = packh(e2, e3);
            } else if (EPI == 3) {
                const float i0 = invrs[row0], i1 = invrs[row0 + 8];
                *(float2*)(Cf + row0 * ldc + col) =
                    make_float2(acc[mt][nt][0] * i0, acc[mt][nt][1] * i0);
                *(float2*)(Cf + (row0 + 8) * ldc + col) =
                    make_float2(acc[mt][nt][2] * i1, acc[mt][nt][3] * i1);
            } else { // EPI == 4
                *(uint32_t*)(Ch + row0 * ldc + col) =
                    packh(__float2half_rn(acc[mt][nt][0]), __float2half_rn(acc[mt][nt][1]));
                *(uint32_t*)(Ch + (row0 + 8) * ldc + col) =
                    packh(__float2half_rn(acc[mt][nt][2]), __float2half_rn(acc[mt][nt][3]));
            }
        }
        if (EPI == 2) {
            p0 += __shfl_xor_sync(0xffffffffu, p0, 1);
            p0 += __shfl_xor_sync(0xffffffffu, p0, 2);
            p1 += __shfl_xor_sync(0xffffffffu, p1, 1);
            p1 += __shfl_xor_sync(0xffffffffu, p1, 2);
            if (t == 0) {
                const int row0 = bm + wm * 64 + mt * 16 + g;
                part[(size_t)row0 * 32 + bx * 2 + wn]       = p0;
                part[(size_t)(row0 + 8) * 32 + bx * 2 + wn] = p1;
            }
        }
    }
}

// ---------------------------------------------------------------------------
// 64x64 both-split 3-MMA (M'), single fp16 out. (256 threads, unchanged)
// ---------------------------------------------------------------------------
constexpr int SUB64 = 64 * 128;
constexpr int STAGE64 = 2 * SUB64;
constexpr int GSMEM64 = 3 * STAGE64;   // 48 KB

__device__ __forceinline__ void fill64(uint32_t dst, const hf* __restrict__ H,
                                       const hf* __restrict__ L,
                                       size_t ld, int rowbase, int k0, int tid) {
#pragma unroll
    for (int p = 0; p < 2; p++) {
        int idx = tid + p * 256;
        int r = idx >> 3, c = idx & 7;
        uint32_t off = (uint32_t)(r * 128) + ((((uint32_t)c) ^ ((uint32_t)r & 7)) << 4);
        const hf* src = (c < 4)
            ? H + (size_t)(rowbase + r) * ld + k0 + c * 8
            : L + (size_t)(rowbase + r) * ld + k0 + (c - 4) * 8;
        cp16s(dst + off, src);
    }
}

__device__ __forceinline__ void gemm64_body(
    char* smem,
    const hf* __restrict__ Ah, const hf* __restrict__ Al,
    const hf* __restrict__ Bh, const hf* __restrict__ Bl,
    hf* __restrict__ Cs, int K, size_t ld, int bm, int bn)
{
    const uint32_t sbase = smem_u32(smem);
    const int tid = threadIdx.x;
    const int wid = tid >> 5, lane = tid & 31;
    const int wm = wid >> 1, wn = wid & 1;
    const int grp = lane >> 3, wi = lane & 7;
    const uint32_t xw = (uint32_t)wi << 4;
    const uint32_t aRow = (uint32_t)(wm * 16 + (grp & 1) * 8 + wi) * 128;
    const uint32_t bRow = (uint32_t)(wn * 32 + (grp >> 1) * 8 + wi) * 128;

    float acc[4][4];
#pragma unroll
    for (int j = 0; j < 4; j++)
#pragma unroll
        for (int r = 0; r < 4; r++) acc[j][r] = 0.f;

    auto fill_stage = [&](int s, int kt) {
        const uint32_t st = sbase + (uint32_t)s * STAGE64;
        fill64(st,         Ah, Al, ld, bm, kt * 32, tid);
        fill64(st + SUB64, Bh, Bl, ld, bn, kt * 32, tid);
        cp_commit();
    };

    const int NT = K / 32;
    fill_stage(0, 0);
    fill_stage(1, 1);

    for (int kt = 0; kt < NT; kt++) {
        if (kt + 1 < NT) cp_wait<1>(); else cp_wait<0>();
        __syncthreads();
        if (kt + 2 < NT) fill_stage((kt + 2) % 3, kt + 2);

        const uint32_t st = sbase + (uint32_t)(kt % 3) * STAGE64;
#pragma unroll
        for (int kk = 0; kk < 2; kk++) {
            uint32_t ah[4], al[4];
            const uint32_t ak = ((uint32_t)(kk * 2 + (grp >> 1)) << 4) ^ xw;
            const uint32_t ao = st + aRow + ak;
            ldsm4(ah, ao);
            ldsm4(al, ao ^ 64u);
            const uint32_t bk = ((uint32_t)(kk * 2 + (grp & 1)) << 4) ^ xw;
#pragma unroll
            for (int np = 0; np < 2; np++) {
                uint32_t bh[4], bl[4];
                const uint32_t bo = st + SUB64 + bRow + (uint32_t)np * 2048 + bk;
                ldsm4(bh, bo);
                ldsm4(bl, bo ^ 64u);
#pragma unroll
                for (int half = 0; half < 2; half++) {
                    const int nt = np * 2 + half;
                    const int h = half * 2;
                    mma_fp16(acc[nt], ah, bh[h], bh[h + 1]);
                    mma_fp16(acc[nt], ah, bl[h], bl[h + 1]);
                    mma_fp16(acc[nt], al, bh[h], bh[h + 1]);
                }
            }
        }
    }

    const int g = lane >> 2, t = lane & 3;
#pragma unroll
    for (int nt = 0; nt < 4; nt++) {
        const size_t row0 = (size_t)(bm + wm * 16 + g);
        const size_t col  = (size_t)(bn + wn * 32 + nt * 8 + 2 * t);
        *(uint32_t*)(Cs + row0 * ld + col) =
            packh(__float2half_rn(acc[nt][0]), __float2half_rn(acc[nt][1]));
        *(uint32_t*)(Cs + (row0 + 8) * ld + col) =
            packh(__float2half_rn(acc[nt][2]), __float2half_rn(acc[nt][3]));
    }
}

// ---------------------------------------------------------------------------
// prep1: transpose+split wq, wk
// ---------------------------------------------------------------------------
__global__ __launch_bounds__(256)
void prep1_kernel(const float* __restrict__ wq, hf* __restrict__ wqth, hf* __restrict__ wqtl,
                  const float* __restrict__ wk, hf* __restrict__ wkth, hf* __restrict__ wktl)
{
    __shared__ float tile[32][33];
    const int tb = blockIdx.x & 1023;
    const float* x = (blockIdx.x < 1024) ? wq : wk;
    hf* h = (blockIdx.x < 1024) ? wqth : wkth;
    hf* l = (blockIdx.x < 1024) ? wqtl : wktl;
    const int tx = threadIdx.x & 31, ty = threadIdx.x >> 5;
    const int r0 = (tb >> 5) * 32, c0 = (tb & 31) * 32;
#pragma unroll
    for (int i = 0; i < 4; i++)
        tile[ty + i * 8][tx] = x[(size_t)(r0 + ty + i * 8) * D_ + c0 + tx];
    __syncthreads();
#pragma unroll
    for (int i = 0; i < 4; i++) {
        float vv = tile[tx][ty + i * 8];
        hf hh, ll;
        split2(vv, hh, ll);
        h[(size_t)(c0 + ty + i * 8) * D_ + r0 + tx] = hh;
        l[(size_t)(c0 + ty + i * 8) * D_ + r0 + tx] = ll;
    }
}

// ---------------------------------------------------------------------------
// prep2: [0,256) M' 64x64; then q, k, v, wv single converts.
// ---------------------------------------------------------------------------
__device__ __forceinline__ void single_conv_block(const float* __restrict__ x,
                                                  hf* __restrict__ h, size_t bi) {
    const float4* x4 = (const float4*)x;
    uint2* h2 = (uint2*)h;
    const size_t base = bi * 2048 + threadIdx.x;
#pragma unroll
    for (int j = 0; j < 8; j++) {
        float4 vv = x4[base + j * 256];
        h2[base + j * 256] = make_uint2(
            packh(__float2half_rn(vv.x), __float2half_rn(vv.y)),
            packh(__float2half_rn(vv.z), __float2half_rn(vv.w)));
    }
}

__global__ __launch_bounds__(256, 2)
void prep2_kernel(const hf* __restrict__ wkth, const hf* __restrict__ wktl,
                  const hf* __restrict__ wqth, const hf* __restrict__ wqtl,
                  hf* __restrict__ ms,
                  const float* __restrict__ q, hf* __restrict__ qs,
                  const float* __restrict__ k, hf* __restrict__ ks,
                  const float* __restrict__ v, hf* __restrict__ vs,
                  const float* __restrict__ wv, hf* __restrict__ wvs)
{
    extern __shared__ char smem[];
    const int bx = blockIdx.x;
    if (bx < 256) {
        gemm64_body(smem, wkth, wktl, wqth, wqtl, ms,
                    D_, D_, (bx >> 4) * 64, (bx & 15) * 64);
    } else {
        int b = bx - 256;
        if (b < 1024)       single_conv_block(q, qs, (size_t)b);
        else if (b < 2048)  single_conv_block(k, ks, (size_t)(b - 1024));
        else if (b < 3072)  single_conv_block(v, vs, (size_t)(b - 2048));
        else                single_conv_block(wv, wvs, (size_t)(b - 3072));
    }
}

// ---------------------------------------------------------------------------
// dualproj: qM (512 blocks) + vp^T (512 blocks), single 1-MMA, 128 threads
// ---------------------------------------------------------------------------
__global__ __launch_bounds__(128, 2)
void dualproj_kernel(const hf* qs, const hf* ms, hf* qms,
                     const hf* wvs, const hf* vs, hf* vts)
{
    extern __shared__ char smem[];
    int bx = blockIdx.x;
    if (bx < 512) {
        gemm128_ss_body<4>(smem, qs, ms, D_, D_, D_, qms, nullptr, D_,
                           nullptr, nullptr, (bx >> 3) * 128, (bx & 7) * 128, 0);
    } else {
        bx -= 512;
        gemm128_ss_body<4>(smem, wvs, vs, D_, D_, D_, vts, nullptr, MS_,
                           nullptr, nullptr, (bx >> 6) * 128, (bx & 63) * 128, 0);
    }
}

// scores: e = rn(exp(qM k^T / 32)) + row partials
__global__ __launch_bounds__(128, 2)
void scores_kernel(const hf* __restrict__ qms, const hf* __restrict__ ks,
                   hf* __restrict__ e, float* __restrict__ part)
{
    extern __shared__ char smem[];
    const size_t zq = (size_t)blockIdx.z * S_ * D_;
    gemm128_ss_body<2>(smem, qms + zq, ks + zq, D_, D_, D_,
                       e + (size_t)blockIdx.z * S_ * S_, nullptr, S_,
                       part + (size_t)blockIdx.z * S_ * 32, nullptr,
                       blockIdx.y * 128, blockIdx.x * 128, blockIdx.x);
}

// pv: computes invrs for its 128 rows into smem, then out = diag(invrs) e vp
__global__ __launch_bounds__(128, 2)
void pv_kernel(const hf* __restrict__ e, const hf* __restrict__ vts,
               float* __restrict__ out, const float* __restrict__ part)
{
    extern __shared__ char smem[];
    float* sInv = (float*)(smem + GSMEM_SS);
    const int bm = blockIdx.y * 128;
    const float* pz = part + (size_t)blockIdx.z * S_ * 32;
    {
        const float* pr = pz + (size_t)(bm + threadIdx.x) * 32;
        float s = 0.f;
#pragma unroll
        for (int j = 0; j < 32; j++) s += pr[j];
        sInv[threadIdx.x] = 1.f / s;
    }
    __syncthreads();

    gemm128_ss_body<3>(smem, e + (size_t)blockIdx.z * S_ * S_,
                       vts + (size_t)blockIdx.z * S_, S_, MS_, S_,
                       nullptr, out + (size_t)blockIdx.z * S_ * D_, D_,
                       nullptr, sInv - bm,
                       bm, blockIdx.x * 128, 0);
}

// ---------------------------------------------------------------------------
extern "C" void kernel_launch(void* const* d_in, const int* in_sizes, int n_in,
                              void* d_out, int out_size)
{
    const float* q  = (const float*)d_in[0];
    const float* k  = (const float*)d_in[1];
    const float* v  = (const float*)d_in[2];
    const float* wq = (const float*)d_in[3];
    const float* wk = (const float*)d_in[4];
    const float* wv = (const float*)d_in[5];
    float* out = (float*)d_out;

    hf *qs, *ks, *vs, *wvs;
    hf *wqth, *wqtl, *wkth, *wktl;
    hf *ms, *qms, *vts, *e;
    float *part;
    cudaGetSymbolAddress((void**)&qs, g_qs);     cudaGetSymbolAddress((void**)&ks, g_ks);
    cudaGetSymbolAddress((void**)&vs, g_vs);     cudaGetSymbolAddress((void**)&wvs, g_wvs);
    cudaGetSymbolAddress((void**)&wqth, g_wqth); cudaGetSymbolAddress((void**)&wqtl, g_wqtl);
    cudaGetSymbolAddress((void**)&wkth, g_wkth); cudaGetSymbolAddress((void**)&wktl, g_wktl);
    cudaGetSymbolAddress((void**)&ms, g_ms);     cudaGetSymbolAddress((void**)&qms, g_qms);
    cudaGetSymbolAddress((void**)&vts, g_vts);   cudaGetSymbolAddress((void**)&e, g_e);
    cudaGetSymbolAddress((void**)&part, g_part);

    cudaFuncSetAttribute(prep2_kernel,    cudaFuncAttributeMaxDynamicSharedMemorySize, GSMEM64);
    cudaFuncSetAttribute(dualproj_kernel, cudaFuncAttributeMaxDynamicSharedMemorySize, GSMEM_SS);
    cudaFuncSetAttribute(scores_kernel,   cudaFuncAttributeMaxDynamicSharedMemorySize, GSMEM_SS);
    cudaFuncSetAttribute(pv_kernel,       cudaFuncAttributeMaxDynamicSharedMemorySize, GSMEM_PV);

    // 1) transpose+split wq, wk
    prep1_kernel<<<2048, 256>>>(wq, wqth, wqtl, wk, wkth, wktl);

    // 2) M' (256 blocks) + q/k/v/wv single converts
    prep2_kernel<<<256 + 3 * 1024 + 128, 256, GSMEM64>>>(
        wkth, wktl, wqth, wqtl, ms,
        q, qs, k, ks, v, vs, wv, wvs);

    // 3) qM = q M'^T and vp^T = Wv v^T (one launch)
    dualproj_kernel<<<1024, 128, GSMEM_SS>>>(qs, ms, qms, wvs, vs, vts);

    // 4) e = exp(qM k^T / 32) + row partials
    dim3 gs(16, 16, B_);
    scores_kernel<<<gs, 128, GSMEM_SS>>>(qms, ks, e, part);

    // 5) out = diag(1/rowsum) e vp  (invrs computed in-kernel)
    dim3 go(8, 16, B_);
    pv_kernel<<<go, 128, GSMEM_PV>>>(e, vts, out, part);
}